// round 4
// baseline (speedup 1.0000x reference)
#include <cuda_runtime.h>
#include <cuda_bf16.h>

#define DIM 128
#define N_TOTAL 299593
#define NTOP 37449            // nodes in levels 0..5 (non-leaf)

// Level sizes/offsets for B=8, L=7 perfect tree
static const int H_SIZES[7] = {1, 8, 64, 512, 4096, 32768, 262144};
static const int H_OFFS[8]  = {0, 1, 9, 73, 585, 4681, 37449, 299593};

// ---------------- scratch (device globals; no allocations allowed) ----------------
__device__ float g_agg[NTOP * DIM];       // agg for levels 0..5 (leaves alias initial)
__device__ float g_ctx[N_TOTAL * DIM];    // ctx for every node
__device__ float g_t2 [65536 * DIM];      // per-level tmp (t2 / cth)

// ================= bf16x3 tensor-core GEMM machinery =================
#define SPITCH 136
#define STILE  (128 * SPITCH)
#define EPITCH 132

__device__ __forceinline__ void mma16816(float* c, const unsigned* a,
                                         unsigned b0, unsigned b1)
{
    asm volatile(
        "mma.sync.aligned.m16n8k16.row.col.f32.bf16.bf16.f32 "
        "{%0,%1,%2,%3},{%4,%5,%6,%7},{%8,%9},{%0,%1,%2,%3};\n"
        : "+f"(c[0]), "+f"(c[1]), "+f"(c[2]), "+f"(c[3])
        : "r"(a[0]), "r"(a[1]), "r"(a[2]), "r"(a[3]), "r"(b0), "r"(b1));
}

// Stage a 128x128 fp32 tile into bf16 hi/lo smem tiles (pitch SPITCH).
__device__ __forceinline__ void stage_tile(
    const float* __restrict__ G, int rows_valid, int gstride,
    __nv_bfloat16* shi, __nv_bfloat16* slo, int tid)
{
    for (int idx = tid; idx < 128 * 32; idx += 256) {
        int r = idx >> 5, c4 = (idx & 31) * 4;
        float4 v = make_float4(0.f, 0.f, 0.f, 0.f);
        if (r < rows_valid) v = *(const float4*)(G + (size_t)r * gstride + c4);

        __nv_bfloat16 h0 = __float2bfloat16(v.x);
        __nv_bfloat16 h1 = __float2bfloat16(v.y);
        __nv_bfloat16 h2 = __float2bfloat16(v.z);
        __nv_bfloat16 h3 = __float2bfloat16(v.w);
        __nv_bfloat16 l0 = __float2bfloat16(v.x - __bfloat162float(h0));
        __nv_bfloat16 l1 = __float2bfloat16(v.y - __bfloat162float(h1));
        __nv_bfloat16 l2 = __float2bfloat16(v.z - __bfloat162float(h2));
        __nv_bfloat16 l3 = __float2bfloat16(v.w - __bfloat162float(h3));

        uint2 hv, lv;
        hv.x = ((unsigned)__bfloat16_as_ushort(h1) << 16) | __bfloat16_as_ushort(h0);
        hv.y = ((unsigned)__bfloat16_as_ushort(h3) << 16) | __bfloat16_as_ushort(h2);
        lv.x = ((unsigned)__bfloat16_as_ushort(l1) << 16) | __bfloat16_as_ushort(l0);
        lv.y = ((unsigned)__bfloat16_as_ushort(l3) << 16) | __bfloat16_as_ushort(l2);
        *(uint2*)(shi + (size_t)r * SPITCH + c4) = hv;
        *(uint2*)(slo + (size_t)r * SPITCH + c4) = lv;
    }
}

// Stage with per-row source select: row < bnd -> A, else B (both row-major, stride 128).
__device__ __forceinline__ void stage_tile_sel(
    const float* __restrict__ A, const float* __restrict__ B, int bnd,
    int grow0, int M, __nv_bfloat16* shi, __nv_bfloat16* slo, int tid)
{
    for (int idx = tid; idx < 128 * 32; idx += 256) {
        int r = idx >> 5, c4 = (idx & 31) * 4;
        int gr = grow0 + r;
        float4 v = make_float4(0.f, 0.f, 0.f, 0.f);
        if (gr < M) {
            const float* src = (gr < bnd) ? A : B;
            v = *(const float4*)(src + (size_t)gr * 128 + c4);
        }
        __nv_bfloat16 h0 = __float2bfloat16(v.x);
        __nv_bfloat16 h1 = __float2bfloat16(v.y);
        __nv_bfloat16 h2 = __float2bfloat16(v.z);
        __nv_bfloat16 h3 = __float2bfloat16(v.w);
        __nv_bfloat16 l0 = __float2bfloat16(v.x - __bfloat162float(h0));
        __nv_bfloat16 l1 = __float2bfloat16(v.y - __bfloat162float(h1));
        __nv_bfloat16 l2 = __float2bfloat16(v.z - __bfloat162float(h2));
        __nv_bfloat16 l3 = __float2bfloat16(v.w - __bfloat162float(h3));
        uint2 hv, lv;
        hv.x = ((unsigned)__bfloat16_as_ushort(h1) << 16) | __bfloat16_as_ushort(h0);
        hv.y = ((unsigned)__bfloat16_as_ushort(h3) << 16) | __bfloat16_as_ushort(h2);
        lv.x = ((unsigned)__bfloat16_as_ushort(l1) << 16) | __bfloat16_as_ushort(l0);
        lv.y = ((unsigned)__bfloat16_as_ushort(l3) << 16) | __bfloat16_as_ushort(l2);
        *(uint2*)(shi + (size_t)r * SPITCH + c4) = hv;
        *(uint2*)(slo + (size_t)r * SPITCH + c4) = lv;
    }
}

__device__ __forceinline__ void panel_mma(
    const __nv_bfloat16* sWhi, const __nv_bfloat16* sWlo,
    const __nv_bfloat16* sXhi, const __nv_bfloat16* sXlo,
    int warp, int g, int tg, float C[16][4])
{
    const int arow = warp * 16 + g;
#pragma unroll
    for (int kc = 0; kc < 8; kc++) {
        const int ko = kc * 16 + tg * 2;
        const __nv_bfloat16* pa = sXhi + arow * SPITCH + ko;
        const __nv_bfloat16* pl = sXlo + arow * SPITCH + ko;
        unsigned ah[4], al[4];
        ah[0] = *(const unsigned*)(pa);
        ah[1] = *(const unsigned*)(pa + 8 * SPITCH);
        ah[2] = *(const unsigned*)(pa + 8);
        ah[3] = *(const unsigned*)(pa + 8 * SPITCH + 8);
        al[0] = *(const unsigned*)(pl);
        al[1] = *(const unsigned*)(pl + 8 * SPITCH);
        al[2] = *(const unsigned*)(pl + 8);
        al[3] = *(const unsigned*)(pl + 8 * SPITCH + 8);
#pragma unroll
        for (int t = 0; t < 16; t++) {
            const __nv_bfloat16* pb  = sWhi + (t * 8 + g) * SPITCH + ko;
            const __nv_bfloat16* pbl = sWlo + (t * 8 + g) * SPITCH + ko;
            unsigned bh0 = *(const unsigned*)(pb);
            unsigned bh1 = *(const unsigned*)(pb + 8);
            unsigned bl0 = *(const unsigned*)(pbl);
            unsigned bl1 = *(const unsigned*)(pbl + 8);
            mma16816(C[t], ah, bh0, bh1);
            mma16816(C[t], ah, bl0, bl1);
            mma16816(C[t], al, bh0, bh1);
        }
    }
}

__device__ __forceinline__ void zero_C(float C[16][4])
{
#pragma unroll
    for (int t = 0; t < 16; t++) {
        C[t][0] = C[t][1] = C[t][2] = C[t][3] = 0.f;
    }
}

// Write relu(C + bias) into fp32 smem buffer sE (128 x 128, pitch EPITCH).
__device__ __forceinline__ void epilogue_to_smem(
    const float C[16][4], const float* __restrict__ bias,
    float* sE, int warp, int g, int tg)
{
    const int r0 = warp * 16 + g, r1 = r0 + 8;
#pragma unroll
    for (int t = 0; t < 16; t++) {
        int c = t * 8 + tg * 2;
        float2 bv = *(const float2*)(bias + c);
        sE[r0 * EPITCH + c]     = fmaxf(C[t][0] + bv.x, 0.f);
        sE[r0 * EPITCH + c + 1] = fmaxf(C[t][1] + bv.y, 0.f);
        sE[r1 * EPITCH + c]     = fmaxf(C[t][2] + bv.x, 0.f);
        sE[r1 * EPITCH + c + 1] = fmaxf(C[t][3] + bv.y, 0.f);
    }
}

// mean over 4 consecutive rows -> T2 rows [og0, og0+32)
__device__ __forceinline__ void mean4_epilogue(
    const float* sE, float* __restrict__ T2, int og0, int G, int tid)
{
    int col = tid & 127, q0 = (tid >> 7) * 16;
    for (int i = 0; i < 16; i++) {
        int q = q0 + i, og = og0 + q;
        if (og < G) {
            float v = sE[(4 * q) * EPITCH + col] + sE[(4 * q + 1) * EPITCH + col]
                    + sE[(4 * q + 2) * EPITCH + col] + sE[(4 * q + 3) * EPITCH + col];
            T2[(size_t)og * 128 + col] = 0.25f * v;
        }
    }
}

// out = init + 0.5 * (pair sum) -> rows [og0, og0+64)
__device__ __forceinline__ void pairadd_epilogue(
    const float* sE, const float* __restrict__ init, float* __restrict__ OUT,
    int og0, int Mout, int tid)
{
    int col = tid & 127, q0 = (tid >> 7) * 32;
    for (int i = 0; i < 32; i++) {
        int q = q0 + i, og = og0 + q;
        if (og < Mout) {
            float v = sE[(2 * q) * EPITCH + col] + sE[(2 * q + 1) * EPITCH + col];
            OUT[(size_t)og * 128 + col] = init[(size_t)og * 128 + col] + 0.5f * v;
        }
    }
}

// ctx combine: out[r] = 0.25*(cth[r>>3] + group4sum - h[r]) for rows [row0, row0+128)
__device__ __forceinline__ void combine_epilogue(
    const float* sE, const float* __restrict__ CTH, float* __restrict__ OUT,
    int row0, int M1, int tid)
{
    int col = tid & 127, q0 = (tid >> 7) * 16;
    for (int i = 0; i < 16; i++) {
        int q = q0 + i;
        int base = row0 + 4 * q;
        if (base < M1) {
            float s = sE[(4 * q) * EPITCH + col] + sE[(4 * q + 1) * EPITCH + col]
                    + sE[(4 * q + 2) * EPITCH + col] + sE[(4 * q + 3) * EPITCH + col];
            float tot = CTH[(size_t)(base >> 3) * 128 + col] + s;
#pragma unroll
            for (int s4 = 0; s4 < 4; s4++)
                OUT[(size_t)(base + s4) * 128 + col] =
                    0.25f * (tot - sE[(4 * q + s4) * EPITCH + col]);
        }
    }
}

// ================= kernels =================

// Plain Y = relu(X @ W^T + b), K=128 (used for down-pass cth).
__global__ void __launch_bounds__(256) gemm_relu(
    const float* __restrict__ X, const float* __restrict__ W,
    const float* __restrict__ bias, float* __restrict__ Y, int M)
{
    extern __shared__ __nv_bfloat16 sm[];
    __nv_bfloat16 *sWhi = sm, *sWlo = sm + STILE, *sXhi = sm + 2 * STILE, *sXlo = sm + 3 * STILE;
    const int tid = threadIdx.x, lane = tid & 31, warp = tid >> 5;
    const int g = lane >> 2, tg = lane & 3;
    const int row0 = blockIdx.x * 128;

    stage_tile(W, 128, 128, sWhi, sWlo, tid);
    stage_tile(X + (size_t)row0 * 128, M - row0, 128, sXhi, sXlo, tid);
    __syncthreads();
    float C[16][4]; zero_C(C);
    panel_mma(sWhi, sWlo, sXhi, sXlo, warp, g, tg, C);

    const int r0 = row0 + warp * 16 + g, r1 = r0 + 8;
#pragma unroll
    for (int t = 0; t < 16; t++) {
        int c = t * 8 + tg * 2;
        float2 bv = *(const float2*)(bias + c);
        if (r0 < M) *(float2*)(Y + (size_t)r0 * 128 + c) =
            make_float2(fmaxf(C[t][0] + bv.x, 0.f), fmaxf(C[t][1] + bv.y, 0.f));
        if (r1 < M) *(float2*)(Y + (size_t)r1 * 128 + c) =
            make_float2(fmaxf(C[t][2] + bv.x, 0.f), fmaxf(C[t][3] + bv.y, 0.f));
    }
}

// Up A: T2 = mean4(relu(X @ Ws^T + bs)) over sibling groups.
__global__ void __launch_bounds__(256) up_gemm_mean4(
    const float* __restrict__ X, const float* __restrict__ W,
    const float* __restrict__ bias, float* __restrict__ T2, int M1)
{
    extern __shared__ __nv_bfloat16 sm[];
    __nv_bfloat16 *sWhi = sm, *sWlo = sm + STILE, *sXhi = sm + 2 * STILE, *sXlo = sm + 3 * STILE;
    float* sE = (float*)(sm + 2 * STILE);
    const int tid = threadIdx.x, lane = tid & 31, warp = tid >> 5;
    const int g = lane >> 2, tg = lane & 3;
    const int row0 = blockIdx.x * 128;

    stage_tile(W, 128, 128, sWhi, sWlo, tid);
    stage_tile(X + (size_t)row0 * 128, M1 - row0, 128, sXhi, sXlo, tid);
    __syncthreads();
    float C[16][4]; zero_C(C);
    panel_mma(sWhi, sWlo, sXhi, sXlo, warp, g, tg, C);
    __syncthreads();
    epilogue_to_smem(C, bias, sE, warp, g, tg);
    __syncthreads();
    mean4_epilogue(sE, T2, row0 >> 2, M1 >> 2, tid);
}

// Up B: AGG = init + 0.5 * pairsum(relu(T2 @ Wc^T + bc)).
__global__ void __launch_bounds__(256) up_gemm_pairadd(
    const float* __restrict__ X, const float* __restrict__ W,
    const float* __restrict__ bias, const float* __restrict__ init,
    float* __restrict__ AGG, int G)
{
    extern __shared__ __nv_bfloat16 sm[];
    __nv_bfloat16 *sWhi = sm, *sWlo = sm + STILE, *sXhi = sm + 2 * STILE, *sXlo = sm + 3 * STILE;
    float* sE = (float*)(sm + 2 * STILE);
    const int tid = threadIdx.x, lane = tid & 31, warp = tid >> 5;
    const int g = lane >> 2, tg = lane & 3;
    const int row0 = blockIdx.x * 128;

    stage_tile(W, 128, 128, sWhi, sWlo, tid);
    stage_tile(X + (size_t)row0 * 128, G - row0, 128, sXhi, sXlo, tid);
    __syncthreads();
    float C[16][4]; zero_C(C);
    panel_mma(sWhi, sWlo, sXhi, sXlo, warp, g, tg, C);
    __syncthreads();
    epilogue_to_smem(C, bias, sE, warp, g, tg);
    __syncthreads();
    pairadd_epilogue(sE, init, AGG, row0 >> 1, G >> 1, tid);
}

// Down D: CTX_child = combine(relu(X @ Wx^T + bx), CTH).
__global__ void __launch_bounds__(256) down_gemm_combine(
    const float* __restrict__ X, const float* __restrict__ W,
    const float* __restrict__ bias, const float* __restrict__ CTH,
    float* __restrict__ OUT, int M1)
{
    extern __shared__ __nv_bfloat16 sm[];
    __nv_bfloat16 *sWhi = sm, *sWlo = sm + STILE, *sXhi = sm + 2 * STILE, *sXlo = sm + 3 * STILE;
    float* sE = (float*)(sm + 2 * STILE);
    const int tid = threadIdx.x, lane = tid & 31, warp = tid >> 5;
    const int g = lane >> 2, tg = lane & 3;
    const int row0 = blockIdx.x * 128;

    stage_tile(W, 128, 128, sWhi, sWlo, tid);
    stage_tile(X + (size_t)row0 * 128, M1 - row0, 128, sXhi, sXlo, tid);
    __syncthreads();
    float C[16][4]; zero_C(C);
    panel_mma(sWhi, sWlo, sXhi, sXlo, warp, g, tg, C);
    __syncthreads();
    epilogue_to_smem(C, bias, sE, warp, g, tg);
    __syncthreads();
    combine_epilogue(sE, CTH, OUT, row0, M1, tid);
}

// Small up level (single block): whole level chain Ws->mean4->Wc->pairadd.
__global__ void __launch_bounds__(256) up_small(
    const float* __restrict__ Xc, const float* __restrict__ init_l,
    float* __restrict__ AGG,
    const float* __restrict__ Ws, const float* __restrict__ bs,
    const float* __restrict__ Wc, const float* __restrict__ bc,
    float* __restrict__ T2, int M1)
{
    extern __shared__ __nv_bfloat16 sm[];
    __nv_bfloat16 *sWhi = sm, *sWlo = sm + STILE, *sXhi = sm + 2 * STILE, *sXlo = sm + 3 * STILE;
    float* sE = (float*)(sm + 2 * STILE);
    const int tid = threadIdx.x, lane = tid & 31, warp = tid >> 5;
    const int g = lane >> 2, tg = lane & 3;
    const int G = M1 >> 2, Mout = M1 >> 3;

    stage_tile(Ws, 128, 128, sWhi, sWlo, tid);
    const int nt = (M1 + 127) / 128;
    for (int tile = 0; tile < nt; tile++) {
        __syncthreads();
        stage_tile(Xc + (size_t)tile * 128 * 128, M1 - tile * 128, 128, sXhi, sXlo, tid);
        __syncthreads();
        float C[16][4]; zero_C(C);
        panel_mma(sWhi, sWlo, sXhi, sXlo, warp, g, tg, C);
        __syncthreads();
        epilogue_to_smem(C, bs, sE, warp, g, tg);
        __syncthreads();
        mean4_epilogue(sE, T2, tile * 32, G, tid);
    }
    __syncthreads();
    stage_tile(Wc, 128, 128, sWhi, sWlo, tid);
    const int nt2 = (G + 127) / 128;
    for (int tile = 0; tile < nt2; tile++) {
        __syncthreads();
        stage_tile(T2 + (size_t)tile * 128 * 128, G - tile * 128, 128, sXhi, sXlo, tid);
        __syncthreads();
        float C[16][4]; zero_C(C);
        panel_mma(sWhi, sWlo, sXhi, sXlo, warp, g, tg, C);
        __syncthreads();
        epilogue_to_smem(C, bc, sE, warp, g, tg);
        __syncthreads();
        pairadd_epilogue(sE, init_l, AGG, tile * 64, Mout, tid);
    }
}

// Small down level (single block): cth = relu(Wx@ctx), then child combine.
__global__ void __launch_bounds__(256) down_small(
    const float* __restrict__ ctx_l, const float* __restrict__ aggc,
    const float* __restrict__ Wx, const float* __restrict__ bx,
    float* __restrict__ T2, float* __restrict__ ctx_out, int Ml, int M1)
{
    extern __shared__ __nv_bfloat16 sm[];
    __nv_bfloat16 *sWhi = sm, *sWlo = sm + STILE, *sXhi = sm + 2 * STILE, *sXlo = sm + 3 * STILE;
    float* sE = (float*)(sm + 2 * STILE);
    const int tid = threadIdx.x, lane = tid & 31, warp = tid >> 5;
    const int g = lane >> 2, tg = lane & 3;

    stage_tile(Wx, 128, 128, sWhi, sWlo, tid);
    // phase 1: cth (Ml <= 128 rows)
    stage_tile(ctx_l, Ml, 128, sXhi, sXlo, tid);
    __syncthreads();
    {
        float C[16][4]; zero_C(C);
        panel_mma(sWhi, sWlo, sXhi, sXlo, warp, g, tg, C);
        const int r0 = warp * 16 + g, r1 = r0 + 8;
#pragma unroll
        for (int t = 0; t < 16; t++) {
            int c = t * 8 + tg * 2;
            float2 bv = *(const float2*)(bx + c);
            if (r0 < Ml) *(float2*)(T2 + (size_t)r0 * 128 + c) =
                make_float2(fmaxf(C[t][0] + bv.x, 0.f), fmaxf(C[t][1] + bv.y, 0.f));
            if (r1 < Ml) *(float2*)(T2 + (size_t)r1 * 128 + c) =
                make_float2(fmaxf(C[t][2] + bv.x, 0.f), fmaxf(C[t][3] + bv.y, 0.f));
        }
    }
    // phase 2: children
    const int nt = (M1 + 127) / 128;
    for (int tile = 0; tile < nt; tile++) {
        __syncthreads();
        stage_tile(aggc + (size_t)tile * 128 * 128, M1 - tile * 128, 128, sXhi, sXlo, tid);
        __syncthreads();
        float C[16][4]; zero_C(C);
        panel_mma(sWhi, sWlo, sXhi, sXlo, warp, g, tg, C);
        __syncthreads();
        epilogue_to_smem(C, bx, sE, warp, g, tg);
        __syncthreads();
        combine_epilogue(sE, T2, ctx_out, tile * 128, M1, tid);
    }
}

// Fused final: out[i] = bh + Wh . relu(Wf @ [ctx_i; agg_i] + bf), K=256.
__global__ void __launch_bounds__(256) final_bf16x3(
    const float* __restrict__ CTX,
    const float* __restrict__ AGGa, const float* __restrict__ AGGb, int bnd,
    const float* __restrict__ Wf, const float* __restrict__ bf,
    const float* __restrict__ Wh, const float* __restrict__ bh,
    float* __restrict__ out, int M)
{
    extern __shared__ __nv_bfloat16 sm[];
    __nv_bfloat16 *sWhi = sm, *sWlo = sm + STILE, *sXhi = sm + 2 * STILE, *sXlo = sm + 3 * STILE;
    const int tid = threadIdx.x, lane = tid & 31, warp = tid >> 5;
    const int g = lane >> 2, tg = lane & 3;
    const int row0 = blockIdx.x * 128;

    float C[16][4]; zero_C(C);
    for (int p = 0; p < 2; p++) {
        __syncthreads();
        stage_tile(Wf + p * 128, 128, 256, sWhi, sWlo, tid);
        if (p == 0)
            stage_tile(CTX + (size_t)row0 * 128, M - row0, 128, sXhi, sXlo, tid);
        else
            stage_tile_sel(AGGa, AGGb, bnd, row0, M, sXhi, sXlo, tid);
        __syncthreads();
        panel_mma(sWhi, sWlo, sXhi, sXlo, warp, g, tg, C);
    }

    float s0 = 0.f, s1 = 0.f;
#pragma unroll
    for (int t = 0; t < 16; t++) {
        int c = t * 8 + tg * 2;
        float2 bv = *(const float2*)(bf + c);
        float2 wv = *(const float2*)(Wh + c);
        s0 += fmaxf(C[t][0] + bv.x, 0.f) * wv.x + fmaxf(C[t][1] + bv.y, 0.f) * wv.y;
        s1 += fmaxf(C[t][2] + bv.x, 0.f) * wv.x + fmaxf(C[t][3] + bv.y, 0.f) * wv.y;
    }
    s0 += __shfl_xor_sync(0xffffffffu, s0, 1);
    s0 += __shfl_xor_sync(0xffffffffu, s0, 2);
    s1 += __shfl_xor_sync(0xffffffffu, s1, 1);
    s1 += __shfl_xor_sync(0xffffffffu, s1, 2);

    if (tg == 0) {
        const int r0 = row0 + warp * 16 + g, r1 = r0 + 8;
        float bhv = bh[0];
        if (r0 < M) out[r0] = s0 + bhv;
        if (r1 < M) out[r1] = s1 + bhv;
    }
}

__global__ void set_ones(float* p, int n)
{
    int i = blockIdx.x * blockDim.x + threadIdx.x;
    if (i < n) p[i] = 1.0f;
}

// ---------------- launch ----------------
extern "C" void kernel_launch(void* const* d_in, const int* in_sizes, int n_in,
                              void* d_out, int out_size)
{
    const float* initial = (const float*)d_in[0];
    const float* Ws = (const float*)d_in[1];
    const float* bs = (const float*)d_in[2];
    const float* Wc = (const float*)d_in[3];
    const float* bc = (const float*)d_in[4];
    const float* Wx = (const float*)d_in[5];
    const float* bx = (const float*)d_in[6];
    const float* Wf = (const float*)d_in[7];
    const float* bf = (const float*)d_in[8];
    const float* Wh = (const float*)d_in[9];
    const float* bh = (const float*)d_in[10];
    float* out = (float*)d_out;

    float *p_agg, *p_ctx, *p_t2;
    cudaGetSymbolAddress((void**)&p_agg, g_agg);
    cudaGetSymbolAddress((void**)&p_ctx, g_ctx);
    cudaGetSymbolAddress((void**)&p_t2,  g_t2);

    const int SMEM_T = 4 * STILE * (int)sizeof(__nv_bfloat16);  // 139264 B
    cudaFuncSetAttribute(gemm_relu,         cudaFuncAttributeMaxDynamicSharedMemorySize, SMEM_T);
    cudaFuncSetAttribute(up_gemm_mean4,     cudaFuncAttributeMaxDynamicSharedMemorySize, SMEM_T);
    cudaFuncSetAttribute(up_gemm_pairadd,   cudaFuncAttributeMaxDynamicSharedMemorySize, SMEM_T);
    cudaFuncSetAttribute(down_gemm_combine, cudaFuncAttributeMaxDynamicSharedMemorySize, SMEM_T);
    cudaFuncSetAttribute(up_small,          cudaFuncAttributeMaxDynamicSharedMemorySize, SMEM_T);
    cudaFuncSetAttribute(down_small,        cudaFuncAttributeMaxDynamicSharedMemorySize, SMEM_T);
    cudaFuncSetAttribute(final_bf16x3,      cudaFuncAttributeMaxDynamicSharedMemorySize, SMEM_T);

    const float* leaf_agg = initial + (size_t)H_OFFS[6] * DIM;  // leaves alias

    // ---- up pass: big levels l = 5,4,3 (2 kernels each) ----
    for (int l = 5; l >= 3; l--) {
        int M1 = H_SIZES[l + 1];
        int G  = M1 >> 2;
        const float* Xc = (l == 5) ? leaf_agg : (p_agg + (size_t)H_OFFS[l + 1] * DIM);

        up_gemm_mean4<<<M1 / 128, 256, SMEM_T>>>(Xc, Ws, bs, p_t2, M1);
        up_gemm_pairadd<<<G / 128, 256, SMEM_T>>>(
            p_t2, Wc, bc,
            initial + (size_t)H_OFFS[l] * DIM,
            p_agg + (size_t)H_OFFS[l] * DIM, G);
    }
    // ---- up pass: small levels l = 2,1,0 (1 kernel each) ----
    for (int l = 2; l >= 0; l--) {
        int M1 = H_SIZES[l + 1];
        up_small<<<1, 256, SMEM_T>>>(
            p_agg + (size_t)H_OFFS[l + 1] * DIM,
            initial + (size_t)H_OFFS[l] * DIM,
            p_agg + (size_t)H_OFFS[l] * DIM,
            Ws, bs, Wc, bc, p_t2, M1);
    }

    // ---- down pass ----
    set_ones<<<1, 128>>>(p_ctx, DIM);   // root ctx = ones
    for (int l = 0; l < 3; l++) {       // small levels, 1 kernel each
        int Ml = H_SIZES[l], M1 = H_SIZES[l + 1];
        down_small<<<1, 256, SMEM_T>>>(
            p_ctx + (size_t)H_OFFS[l] * DIM,
            p_agg + (size_t)H_OFFS[l + 1] * DIM,
            Wx, bx, p_t2,
            p_ctx + (size_t)H_OFFS[l + 1] * DIM, Ml, M1);
    }
    for (int l = 3; l < 6; l++) {       // big levels, 2 kernels each
        int Ml = H_SIZES[l], M1 = H_SIZES[l + 1];
        const float* Xc = (l == 5) ? leaf_agg : (p_agg + (size_t)H_OFFS[l + 1] * DIM);

        gemm_relu<<<(Ml + 127) / 128, 256, SMEM_T>>>(
            p_ctx + (size_t)H_OFFS[l] * DIM, Wx, bx, p_t2, Ml);
        down_gemm_combine<<<M1 / 128, 256, SMEM_T>>>(
            Xc, Wx, bx, p_t2,
            p_ctx + (size_t)H_OFFS[l + 1] * DIM, M1);
    }

    // ---- final ----
    final_bf16x3<<<(N_TOTAL + 127) / 128, 256, SMEM_T>>>(
        p_ctx, p_agg, initial, NTOP,
        Wf, bf, Wh, bh, out, N_TOTAL);
}

// round 5
// speedup vs baseline: 1.3400x; 1.3400x over previous
#include <cuda_runtime.h>
#include <cuda_bf16.h>

#define DIM 128
#define N_TOTAL 299593
#define NTOP 37449

static const int H_SIZES[7] = {1, 8, 64, 512, 4096, 32768, 262144};
static const int H_OFFS[8]  = {0, 1, 9, 73, 585, 4681, 37449, 299593};

// ---------------- scratch ----------------
__device__ float g_agg[NTOP * DIM];
__device__ float g_ctx[N_TOTAL * DIM];
__device__ float g_t2 [65536 * DIM];

// ================= bf16x3 tensor-core GEMM machinery =================
#define SPITCH 136
#define STILE  (128 * SPITCH)          // one 128-row bf16 tile
#define XTILE  (256 * SPITCH)          // one 256-row bf16 tile
#define EPITCH 132

__device__ __forceinline__ void mma16816(float* c, const unsigned* a,
                                         unsigned b0, unsigned b1)
{
    asm volatile(
        "mma.sync.aligned.m16n8k16.row.col.f32.bf16.bf16.f32 "
        "{%0,%1,%2,%3},{%4,%5,%6,%7},{%8,%9},{%0,%1,%2,%3};\n"
        : "+f"(c[0]), "+f"(c[1]), "+f"(c[2]), "+f"(c[3])
        : "r"(a[0]), "r"(a[1]), "r"(a[2]), "r"(a[3]), "r"(b0), "r"(b1));
}

// Stage an nrows x 128 fp32 tile into bf16 hi/lo smem tiles (pitch SPITCH).
__device__ __forceinline__ void stage_tile(
    const float* __restrict__ G, int nrows, int rows_valid, int gstride,
    __nv_bfloat16* shi, __nv_bfloat16* slo, int tid)
{
    for (int idx = tid; idx < nrows * 32; idx += 256) {
        int r = idx >> 5, c4 = (idx & 31) * 4;
        float4 v = make_float4(0.f, 0.f, 0.f, 0.f);
        if (r < rows_valid) v = *(const float4*)(G + (size_t)r * gstride + c4);

        __nv_bfloat16 h0 = __float2bfloat16(v.x);
        __nv_bfloat16 h1 = __float2bfloat16(v.y);
        __nv_bfloat16 h2 = __float2bfloat16(v.z);
        __nv_bfloat16 h3 = __float2bfloat16(v.w);
        __nv_bfloat16 l0 = __float2bfloat16(v.x - __bfloat162float(h0));
        __nv_bfloat16 l1 = __float2bfloat16(v.y - __bfloat162float(h1));
        __nv_bfloat16 l2 = __float2bfloat16(v.z - __bfloat162float(h2));
        __nv_bfloat16 l3 = __float2bfloat16(v.w - __bfloat162float(h3));

        uint2 hv, lv;
        hv.x = ((unsigned)__bfloat16_as_ushort(h1) << 16) | __bfloat16_as_ushort(h0);
        hv.y = ((unsigned)__bfloat16_as_ushort(h3) << 16) | __bfloat16_as_ushort(h2);
        lv.x = ((unsigned)__bfloat16_as_ushort(l1) << 16) | __bfloat16_as_ushort(l0);
        lv.y = ((unsigned)__bfloat16_as_ushort(l3) << 16) | __bfloat16_as_ushort(l2);
        *(uint2*)(shi + (size_t)r * SPITCH + c4) = hv;
        *(uint2*)(slo + (size_t)r * SPITCH + c4) = lv;
    }
}

// 256-row stage with per-row source select (row<bnd -> A else B, stride 128).
__device__ __forceinline__ void stage_tile_sel(
    const float* __restrict__ A, const float* __restrict__ B, int bnd,
    int grow0, int M, __nv_bfloat16* shi, __nv_bfloat16* slo, int tid)
{
    for (int idx = tid; idx < 256 * 32; idx += 256) {
        int r = idx >> 5, c4 = (idx & 31) * 4;
        int gr = grow0 + r;
        float4 v = make_float4(0.f, 0.f, 0.f, 0.f);
        if (gr < M) {
            const float* src = (gr < bnd) ? A : B;
            v = *(const float4*)(src + (size_t)gr * 128 + c4);
        }
        __nv_bfloat16 h0 = __float2bfloat16(v.x);
        __nv_bfloat16 h1 = __float2bfloat16(v.y);
        __nv_bfloat16 h2 = __float2bfloat16(v.z);
        __nv_bfloat16 h3 = __float2bfloat16(v.w);
        __nv_bfloat16 l0 = __float2bfloat16(v.x - __bfloat162float(h0));
        __nv_bfloat16 l1 = __float2bfloat16(v.y - __bfloat162float(h1));
        __nv_bfloat16 l2 = __float2bfloat16(v.z - __bfloat162float(h2));
        __nv_bfloat16 l3 = __float2bfloat16(v.w - __bfloat162float(h3));
        uint2 hv, lv;
        hv.x = ((unsigned)__bfloat16_as_ushort(h1) << 16) | __bfloat16_as_ushort(h0);
        hv.y = ((unsigned)__bfloat16_as_ushort(h3) << 16) | __bfloat16_as_ushort(h2);
        lv.x = ((unsigned)__bfloat16_as_ushort(l1) << 16) | __bfloat16_as_ushort(l0);
        lv.y = ((unsigned)__bfloat16_as_ushort(l3) << 16) | __bfloat16_as_ushort(l2);
        *(uint2*)(shi + (size_t)r * SPITCH + c4) = hv;
        *(uint2*)(slo + (size_t)r * SPITCH + c4) = lv;
    }
}

// ---- 128-row warp mainloop (1 m16 tile per warp) — small kernels ----
__device__ __forceinline__ void panel_mma(
    const __nv_bfloat16* sWhi, const __nv_bfloat16* sWlo,
    const __nv_bfloat16* sXhi, const __nv_bfloat16* sXlo,
    int warp, int g, int tg, float C[16][4])
{
    const int arow = warp * 16 + g;
#pragma unroll
    for (int kc = 0; kc < 8; kc++) {
        const int ko = kc * 16 + tg * 2;
        const __nv_bfloat16* pa = sXhi + arow * SPITCH + ko;
        const __nv_bfloat16* pl = sXlo + arow * SPITCH + ko;
        unsigned ah[4], al[4];
        ah[0] = *(const unsigned*)(pa);
        ah[1] = *(const unsigned*)(pa + 8 * SPITCH);
        ah[2] = *(const unsigned*)(pa + 8);
        ah[3] = *(const unsigned*)(pa + 8 * SPITCH + 8);
        al[0] = *(const unsigned*)(pl);
        al[1] = *(const unsigned*)(pl + 8 * SPITCH);
        al[2] = *(const unsigned*)(pl + 8);
        al[3] = *(const unsigned*)(pl + 8 * SPITCH + 8);
#pragma unroll
        for (int t = 0; t < 16; t++) {
            const __nv_bfloat16* pb  = sWhi + (t * 8 + g) * SPITCH + ko;
            const __nv_bfloat16* pbl = sWlo + (t * 8 + g) * SPITCH + ko;
            unsigned bh0 = *(const unsigned*)(pb);
            unsigned bh1 = *(const unsigned*)(pb + 8);
            unsigned bl0 = *(const unsigned*)(pbl);
            unsigned bl1 = *(const unsigned*)(pbl + 8);
            mma16816(C[t], ah, bh0, bh1);
            mma16816(C[t], ah, bl0, bl1);
            mma16816(C[t], al, bh0, bh1);
        }
    }
}

// ---- 256-row warp mainloop (2 m16 tiles per warp, B reused 2x) ----
__device__ __forceinline__ void panel_mma2(
    const __nv_bfloat16* sWhi, const __nv_bfloat16* sWlo,
    const __nv_bfloat16* sXhi, const __nv_bfloat16* sXlo,
    int warp, int g, int tg, float C[2][16][4])
{
    const int arow0 = warp * 32 + g;
#pragma unroll 2
    for (int kc = 0; kc < 8; kc++) {
        const int ko = kc * 16 + tg * 2;
        unsigned ah0[4], al0[4], ah1[4], al1[4];
        {
            const __nv_bfloat16* pa = sXhi + arow0 * SPITCH + ko;
            const __nv_bfloat16* pl = sXlo + arow0 * SPITCH + ko;
            ah0[0] = *(const unsigned*)(pa);
            ah0[1] = *(const unsigned*)(pa + 8 * SPITCH);
            ah0[2] = *(const unsigned*)(pa + 8);
            ah0[3] = *(const unsigned*)(pa + 8 * SPITCH + 8);
            al0[0] = *(const unsigned*)(pl);
            al0[1] = *(const unsigned*)(pl + 8 * SPITCH);
            al0[2] = *(const unsigned*)(pl + 8);
            al0[3] = *(const unsigned*)(pl + 8 * SPITCH + 8);
        }
        {
            const __nv_bfloat16* pa = sXhi + (arow0 + 16) * SPITCH + ko;
            const __nv_bfloat16* pl = sXlo + (arow0 + 16) * SPITCH + ko;
            ah1[0] = *(const unsigned*)(pa);
            ah1[1] = *(const unsigned*)(pa + 8 * SPITCH);
            ah1[2] = *(const unsigned*)(pa + 8);
            ah1[3] = *(const unsigned*)(pa + 8 * SPITCH + 8);
            al1[0] = *(const unsigned*)(pl);
            al1[1] = *(const unsigned*)(pl + 8 * SPITCH);
            al1[2] = *(const unsigned*)(pl + 8);
            al1[3] = *(const unsigned*)(pl + 8 * SPITCH + 8);
        }
#pragma unroll
        for (int t = 0; t < 16; t++) {
            const __nv_bfloat16* pb  = sWhi + (t * 8 + g) * SPITCH + ko;
            const __nv_bfloat16* pbl = sWlo + (t * 8 + g) * SPITCH + ko;
            unsigned bh0 = *(const unsigned*)(pb);
            unsigned bh1 = *(const unsigned*)(pb + 8);
            unsigned bl0 = *(const unsigned*)(pbl);
            unsigned bl1 = *(const unsigned*)(pbl + 8);
            mma16816(C[0][t], ah0, bh0, bh1);
            mma16816(C[1][t], ah1, bh0, bh1);
            mma16816(C[0][t], ah0, bl0, bl1);
            mma16816(C[1][t], ah1, bl0, bl1);
            mma16816(C[0][t], al0, bh0, bh1);
            mma16816(C[1][t], al1, bh0, bh1);
        }
    }
}

__device__ __forceinline__ void zero_C(float C[16][4])
{
#pragma unroll
    for (int t = 0; t < 16; t++) C[t][0] = C[t][1] = C[t][2] = C[t][3] = 0.f;
}

// epilogue: relu(C+bias) -> smem (128-row variant)
__device__ __forceinline__ void epilogue_to_smem(
    const float C[16][4], const float* __restrict__ bias,
    float* sE, int warp, int g, int tg)
{
    const int r0 = warp * 16 + g, r1 = r0 + 8;
#pragma unroll
    for (int t = 0; t < 16; t++) {
        int c = t * 8 + tg * 2;
        float2 bv = *(const float2*)(bias + c);
        sE[r0 * EPITCH + c]     = fmaxf(C[t][0] + bv.x, 0.f);
        sE[r0 * EPITCH + c + 1] = fmaxf(C[t][1] + bv.y, 0.f);
        sE[r1 * EPITCH + c]     = fmaxf(C[t][2] + bv.x, 0.f);
        sE[r1 * EPITCH + c + 1] = fmaxf(C[t][3] + bv.y, 0.f);
    }
}

// epilogue: relu(C+bias) -> smem (256-row variant)
__device__ __forceinline__ void epilogue_to_smem2(
    const float C[2][16][4], const float* __restrict__ bias,
    float* sE, int warp, int g, int tg)
{
#pragma unroll
    for (int rt = 0; rt < 2; rt++) {
        const int r0 = warp * 32 + rt * 16 + g, r1 = r0 + 8;
#pragma unroll
        for (int t = 0; t < 16; t++) {
            int c = t * 8 + tg * 2;
            float2 bv = *(const float2*)(bias + c);
            sE[r0 * EPITCH + c]     = fmaxf(C[rt][t][0] + bv.x, 0.f);
            sE[r0 * EPITCH + c + 1] = fmaxf(C[rt][t][1] + bv.y, 0.f);
            sE[r1 * EPITCH + c]     = fmaxf(C[rt][t][2] + bv.x, 0.f);
            sE[r1 * EPITCH + c + 1] = fmaxf(C[rt][t][3] + bv.y, 0.f);
        }
    }
}

// ---- smem reduce epilogues; nrows = tile rows (128 or 256) ----
__device__ __forceinline__ void mean4_red(
    const float* sE, float* __restrict__ T2, int og0, int G, int nrows, int tid)
{
    int col = tid & 127;
    for (int q = tid >> 7; q < (nrows >> 2); q += 2) {
        int og = og0 + q;
        if (og < G) {
            float v = sE[(4 * q) * EPITCH + col] + sE[(4 * q + 1) * EPITCH + col]
                    + sE[(4 * q + 2) * EPITCH + col] + sE[(4 * q + 3) * EPITCH + col];
            T2[(size_t)og * 128 + col] = 0.25f * v;
        }
    }
}

__device__ __forceinline__ void pairadd_red(
    const float* sE, const float* __restrict__ init, float* __restrict__ OUT,
    int og0, int Mout, int nrows, int tid)
{
    int col = tid & 127;
    for (int q = tid >> 7; q < (nrows >> 1); q += 2) {
        int og = og0 + q;
        if (og < Mout) {
            float v = sE[(2 * q) * EPITCH + col] + sE[(2 * q + 1) * EPITCH + col];
            OUT[(size_t)og * 128 + col] = init[(size_t)og * 128 + col] + 0.5f * v;
        }
    }
}

__device__ __forceinline__ void combine_red(
    const float* sE, const float* __restrict__ CTH, float* __restrict__ OUT,
    int row0, int M1, int nrows, int tid)
{
    int col = tid & 127;
    for (int q = tid >> 7; q < (nrows >> 2); q += 2) {
        int base = row0 + 4 * q;
        if (base < M1) {
            float s = sE[(4 * q) * EPITCH + col] + sE[(4 * q + 1) * EPITCH + col]
                    + sE[(4 * q + 2) * EPITCH + col] + sE[(4 * q + 3) * EPITCH + col];
            float tot = CTH[(size_t)(base >> 3) * 128 + col] + s;
#pragma unroll
            for (int s4 = 0; s4 < 4; s4++)
                OUT[(size_t)(base + s4) * 128 + col] =
                    0.25f * (tot - sE[(4 * q + s4) * EPITCH + col]);
        }
    }
}

// ================= big-level kernels (256-row tiles) =================
// smem layout: sWhi[STILE], sWlo[STILE], sXhi[XTILE], sXlo[XTILE]; sE aliases X.
#define SMEM_BIG ((2 * STILE + 2 * XTILE) * (int)sizeof(__nv_bfloat16))

__global__ void __launch_bounds__(256, 1) gemm_relu_big(
    const float* __restrict__ X, const float* __restrict__ W,
    const float* __restrict__ bias, float* __restrict__ Y, int M)
{
    extern __shared__ __nv_bfloat16 sm[];
    __nv_bfloat16 *sWhi = sm, *sWlo = sm + STILE;
    __nv_bfloat16 *sXhi = sm + 2 * STILE, *sXlo = sm + 2 * STILE + XTILE;
    const int tid = threadIdx.x, lane = tid & 31, warp = tid >> 5;
    const int g = lane >> 2, tg = lane & 3;
    const int row0 = blockIdx.x * 256;

    stage_tile(W, 128, 128, 128, sWhi, sWlo, tid);
    stage_tile(X + (size_t)row0 * 128, 256, M - row0, 128, sXhi, sXlo, tid);
    __syncthreads();
    float C[2][16][4]; zero_C(C[0]); zero_C(C[1]);
    panel_mma2(sWhi, sWlo, sXhi, sXlo, warp, g, tg, C);

#pragma unroll
    for (int rt = 0; rt < 2; rt++) {
        const int r0 = row0 + warp * 32 + rt * 16 + g, r1 = r0 + 8;
#pragma unroll
        for (int t = 0; t < 16; t++) {
            int c = t * 8 + tg * 2;
            float2 bv = *(const float2*)(bias + c);
            if (r0 < M) *(float2*)(Y + (size_t)r0 * 128 + c) =
                make_float2(fmaxf(C[rt][t][0] + bv.x, 0.f), fmaxf(C[rt][t][1] + bv.y, 0.f));
            if (r1 < M) *(float2*)(Y + (size_t)r1 * 128 + c) =
                make_float2(fmaxf(C[rt][t][2] + bv.x, 0.f), fmaxf(C[rt][t][3] + bv.y, 0.f));
        }
    }
}

__global__ void __launch_bounds__(256, 1) up_mean4_big(
    const float* __restrict__ X, const float* __restrict__ W,
    const float* __restrict__ bias, float* __restrict__ T2, int M1)
{
    extern __shared__ __nv_bfloat16 sm[];
    __nv_bfloat16 *sWhi = sm, *sWlo = sm + STILE;
    __nv_bfloat16 *sXhi = sm + 2 * STILE, *sXlo = sm + 2 * STILE + XTILE;
    float* sE = (float*)(sm + 2 * STILE);
    const int tid = threadIdx.x, lane = tid & 31, warp = tid >> 5;
    const int g = lane >> 2, tg = lane & 3;
    const int row0 = blockIdx.x * 256;

    stage_tile(W, 128, 128, 128, sWhi, sWlo, tid);
    stage_tile(X + (size_t)row0 * 128, 256, M1 - row0, 128, sXhi, sXlo, tid);
    __syncthreads();
    float C[2][16][4]; zero_C(C[0]); zero_C(C[1]);
    panel_mma2(sWhi, sWlo, sXhi, sXlo, warp, g, tg, C);
    __syncthreads();
    epilogue_to_smem2(C, bias, sE, warp, g, tg);
    __syncthreads();
    mean4_red(sE, T2, row0 >> 2, M1 >> 2, 256, tid);
}

__global__ void __launch_bounds__(256, 1) up_pairadd_big(
    const float* __restrict__ X, const float* __restrict__ W,
    const float* __restrict__ bias, const float* __restrict__ init,
    float* __restrict__ AGG, int G)
{
    extern __shared__ __nv_bfloat16 sm[];
    __nv_bfloat16 *sWhi = sm, *sWlo = sm + STILE;
    __nv_bfloat16 *sXhi = sm + 2 * STILE, *sXlo = sm + 2 * STILE + XTILE;
    float* sE = (float*)(sm + 2 * STILE);
    const int tid = threadIdx.x, lane = tid & 31, warp = tid >> 5;
    const int g = lane >> 2, tg = lane & 3;
    const int row0 = blockIdx.x * 256;

    stage_tile(W, 128, 128, 128, sWhi, sWlo, tid);
    stage_tile(X + (size_t)row0 * 128, 256, G - row0, 128, sXhi, sXlo, tid);
    __syncthreads();
    float C[2][16][4]; zero_C(C[0]); zero_C(C[1]);
    panel_mma2(sWhi, sWlo, sXhi, sXlo, warp, g, tg, C);
    __syncthreads();
    epilogue_to_smem2(C, bias, sE, warp, g, tg);
    __syncthreads();
    pairadd_red(sE, init, AGG, row0 >> 1, G >> 1, 256, tid);
}

__global__ void __launch_bounds__(256, 1) down_combine_big(
    const float* __restrict__ X, const float* __restrict__ W,
    const float* __restrict__ bias, const float* __restrict__ CTH,
    float* __restrict__ OUT, int M1)
{
    extern __shared__ __nv_bfloat16 sm[];
    __nv_bfloat16 *sWhi = sm, *sWlo = sm + STILE;
    __nv_bfloat16 *sXhi = sm + 2 * STILE, *sXlo = sm + 2 * STILE + XTILE;
    float* sE = (float*)(sm + 2 * STILE);
    const int tid = threadIdx.x, lane = tid & 31, warp = tid >> 5;
    const int g = lane >> 2, tg = lane & 3;
    const int row0 = blockIdx.x * 256;

    stage_tile(W, 128, 128, 128, sWhi, sWlo, tid);
    stage_tile(X + (size_t)row0 * 128, 256, M1 - row0, 128, sXhi, sXlo, tid);
    __syncthreads();
    float C[2][16][4]; zero_C(C[0]); zero_C(C[1]);
    panel_mma2(sWhi, sWlo, sXhi, sXlo, warp, g, tg, C);
    __syncthreads();
    epilogue_to_smem2(C, bias, sE, warp, g, tg);
    __syncthreads();
    combine_red(sE, CTH, OUT, row0, M1, 256, tid);
}

// Fused final (256-row): out[i] = bh + Wh . relu(Wf @ [ctx_i; agg_i] + bf)
__global__ void __launch_bounds__(256, 1) final_big(
    const float* __restrict__ CTX,
    const float* __restrict__ AGGa, const float* __restrict__ AGGb, int bnd,
    const float* __restrict__ Wf, const float* __restrict__ bf,
    const float* __restrict__ Wh, const float* __restrict__ bh,
    float* __restrict__ out, int M)
{
    extern __shared__ __nv_bfloat16 sm[];
    __nv_bfloat16 *sWhi = sm, *sWlo = sm + STILE;
    __nv_bfloat16 *sXhi = sm + 2 * STILE, *sXlo = sm + 2 * STILE + XTILE;
    const int tid = threadIdx.x, lane = tid & 31, warp = tid >> 5;
    const int g = lane >> 2, tg = lane & 3;
    const int row0 = blockIdx.x * 256;

    float C[2][16][4]; zero_C(C[0]); zero_C(C[1]);
    for (int p = 0; p < 2; p++) {
        __syncthreads();
        stage_tile(Wf + p * 128, 128, 128, 256, sWhi, sWlo, tid);
        if (p == 0)
            stage_tile(CTX + (size_t)row0 * 128, 256, M - row0, 128, sXhi, sXlo, tid);
        else
            stage_tile_sel(AGGa, AGGb, bnd, row0, M, sXhi, sXlo, tid);
        __syncthreads();
        panel_mma2(sWhi, sWlo, sXhi, sXlo, warp, g, tg, C);
    }

#pragma unroll
    for (int rt = 0; rt < 2; rt++) {
        float s0 = 0.f, s1 = 0.f;
#pragma unroll
        for (int t = 0; t < 16; t++) {
            int c = t * 8 + tg * 2;
            float2 bv = *(const float2*)(bf + c);
            float2 wv = *(const float2*)(Wh + c);
            s0 += fmaxf(C[rt][t][0] + bv.x, 0.f) * wv.x + fmaxf(C[rt][t][1] + bv.y, 0.f) * wv.y;
            s1 += fmaxf(C[rt][t][2] + bv.x, 0.f) * wv.x + fmaxf(C[rt][t][3] + bv.y, 0.f) * wv.y;
        }
        s0 += __shfl_xor_sync(0xffffffffu, s0, 1);
        s0 += __shfl_xor_sync(0xffffffffu, s0, 2);
        s1 += __shfl_xor_sync(0xffffffffu, s1, 1);
        s1 += __shfl_xor_sync(0xffffffffu, s1, 2);
        if (tg == 0) {
            const int r0 = row0 + warp * 32 + rt * 16 + g, r1 = r0 + 8;
            float bhv = bh[0];
            if (r0 < M) out[r0] = s0 + bhv;
            if (r1 < M) out[r1] = s1 + bhv;
        }
    }
}

// ================= tiny-level kernels (single block, 128-row machinery) =================
#define SMEM_SMALL (4 * STILE * (int)sizeof(__nv_bfloat16))

__global__ void __launch_bounds__(256) up_small(
    const float* __restrict__ Xc, const float* __restrict__ init_l,
    float* __restrict__ AGG,
    const float* __restrict__ Ws, const float* __restrict__ bs,
    const float* __restrict__ Wc, const float* __restrict__ bc,
    float* __restrict__ T2, int M1)
{
    extern __shared__ __nv_bfloat16 sm[];
    __nv_bfloat16 *sWhi = sm, *sWlo = sm + STILE, *sXhi = sm + 2 * STILE, *sXlo = sm + 3 * STILE;
    float* sE = (float*)(sm + 2 * STILE);
    const int tid = threadIdx.x, lane = tid & 31, warp = tid >> 5;
    const int g = lane >> 2, tg = lane & 3;
    const int G = M1 >> 2, Mout = M1 >> 3;

    stage_tile(Ws, 128, 128, 128, sWhi, sWlo, tid);
    stage_tile(Xc, 128, M1, 128, sXhi, sXlo, tid);
    __syncthreads();
    {
        float C[16][4]; zero_C(C);
        panel_mma(sWhi, sWlo, sXhi, sXlo, warp, g, tg, C);
        __syncthreads();
        epilogue_to_smem(C, bs, sE, warp, g, tg);
        __syncthreads();
        mean4_red(sE, T2, 0, G, 128, tid);
    }
    __syncthreads();
    stage_tile(Wc, 128, 128, 128, sWhi, sWlo, tid);
    stage_tile(T2, 128, G, 128, sXhi, sXlo, tid);
    __syncthreads();
    {
        float C[16][4]; zero_C(C);
        panel_mma(sWhi, sWlo, sXhi, sXlo, warp, g, tg, C);
        __syncthreads();
        epilogue_to_smem(C, bc, sE, warp, g, tg);
        __syncthreads();
        pairadd_red(sE, init_l, AGG, 0, Mout, 128, tid);
    }
}

__global__ void __launch_bounds__(256) down_small(
    const float* __restrict__ ctx_l, const float* __restrict__ aggc,
    const float* __restrict__ Wx, const float* __restrict__ bx,
    float* __restrict__ T2, float* __restrict__ ctx_out, int Ml, int M1)
{
    extern __shared__ __nv_bfloat16 sm[];
    __nv_bfloat16 *sWhi = sm, *sWlo = sm + STILE, *sXhi = sm + 2 * STILE, *sXlo = sm + 3 * STILE;
    float* sE = (float*)(sm + 2 * STILE);
    const int tid = threadIdx.x, lane = tid & 31, warp = tid >> 5;
    const int g = lane >> 2, tg = lane & 3;

    stage_tile(Wx, 128, 128, 128, sWhi, sWlo, tid);
    stage_tile(ctx_l, 128, Ml, 128, sXhi, sXlo, tid);
    __syncthreads();
    {
        float C[16][4]; zero_C(C);
        panel_mma(sWhi, sWlo, sXhi, sXlo, warp, g, tg, C);
        const int r0 = warp * 16 + g, r1 = r0 + 8;
#pragma unroll
        for (int t = 0; t < 16; t++) {
            int c = t * 8 + tg * 2;
            float2 bv = *(const float2*)(bx + c);
            if (r0 < Ml) *(float2*)(T2 + (size_t)r0 * 128 + c) =
                make_float2(fmaxf(C[t][0] + bv.x, 0.f), fmaxf(C[t][1] + bv.y, 0.f));
            if (r1 < Ml) *(float2*)(T2 + (size_t)r1 * 128 + c) =
                make_float2(fmaxf(C[t][2] + bv.x, 0.f), fmaxf(C[t][3] + bv.y, 0.f));
        }
    }
    __syncthreads();
    stage_tile(aggc, 128, M1, 128, sXhi, sXlo, tid);
    __syncthreads();
    {
        float C[16][4]; zero_C(C);
        panel_mma(sWhi, sWlo, sXhi, sXlo, warp, g, tg, C);
        __syncthreads();
        epilogue_to_smem(C, bx, sE, warp, g, tg);
        __syncthreads();
        combine_red(sE, T2, ctx_out, 0, M1, 128, tid);
    }
}

__global__ void set_ones(float* p, int n)
{
    int i = blockIdx.x * blockDim.x + threadIdx.x;
    if (i < n) p[i] = 1.0f;
}

// ---------------- launch ----------------
extern "C" void kernel_launch(void* const* d_in, const int* in_sizes, int n_in,
                              void* d_out, int out_size)
{
    const float* initial = (const float*)d_in[0];
    const float* Ws = (const float*)d_in[1];
    const float* bs = (const float*)d_in[2];
    const float* Wc = (const float*)d_in[3];
    const float* bc = (const float*)d_in[4];
    const float* Wx = (const float*)d_in[5];
    const float* bx = (const float*)d_in[6];
    const float* Wf = (const float*)d_in[7];
    const float* bf = (const float*)d_in[8];
    const float* Wh = (const float*)d_in[9];
    const float* bh = (const float*)d_in[10];
    float* out = (float*)d_out;

    float *p_agg, *p_ctx, *p_t2;
    cudaGetSymbolAddress((void**)&p_agg, g_agg);
    cudaGetSymbolAddress((void**)&p_ctx, g_ctx);
    cudaGetSymbolAddress((void**)&p_t2,  g_t2);

    cudaFuncSetAttribute(gemm_relu_big,    cudaFuncAttributeMaxDynamicSharedMemorySize, SMEM_BIG);
    cudaFuncSetAttribute(up_mean4_big,     cudaFuncAttributeMaxDynamicSharedMemorySize, SMEM_BIG);
    cudaFuncSetAttribute(up_pairadd_big,   cudaFuncAttributeMaxDynamicSharedMemorySize, SMEM_BIG);
    cudaFuncSetAttribute(down_combine_big, cudaFuncAttributeMaxDynamicSharedMemorySize, SMEM_BIG);
    cudaFuncSetAttribute(final_big,        cudaFuncAttributeMaxDynamicSharedMemorySize, SMEM_BIG);
    cudaFuncSetAttribute(up_small,         cudaFuncAttributeMaxDynamicSharedMemorySize, SMEM_SMALL);
    cudaFuncSetAttribute(down_small,       cudaFuncAttributeMaxDynamicSharedMemorySize, SMEM_SMALL);

    const float* leaf_agg = initial + (size_t)H_OFFS[6] * DIM;

    // ---- up pass: levels 5..2 (2 parallel launches each) ----
    for (int l = 5; l >= 2; l--) {
        int M1 = H_SIZES[l + 1];
        int G  = M1 >> 2;
        const float* Xc = (l == 5) ? leaf_agg : (p_agg + (size_t)H_OFFS[l + 1] * DIM);

        up_mean4_big<<<(M1 + 255) / 256, 256, SMEM_BIG>>>(Xc, Ws, bs, p_t2, M1);
        up_pairadd_big<<<(G + 255) / 256, 256, SMEM_BIG>>>(
            p_t2, Wc, bc,
            initial + (size_t)H_OFFS[l] * DIM,
            p_agg + (size_t)H_OFFS[l] * DIM, G);
    }
    // levels 1, 0: single fused block (one tile each phase)
    for (int l = 1; l >= 0; l--) {
        up_small<<<1, 256, SMEM_SMALL>>>(
            p_agg + (size_t)H_OFFS[l + 1] * DIM,
            initial + (size_t)H_OFFS[l] * DIM,
            p_agg + (size_t)H_OFFS[l] * DIM,
            Ws, bs, Wc, bc, p_t2, H_SIZES[l + 1]);
    }

    // ---- down pass ----
    set_ones<<<1, 128>>>(p_ctx, DIM);
    for (int l = 0; l < 2; l++) {
        down_small<<<1, 256, SMEM_SMALL>>>(
            p_ctx + (size_t)H_OFFS[l] * DIM,
            p_agg + (size_t)H_OFFS[l + 1] * DIM,
            Wx, bx, p_t2,
            p_ctx + (size_t)H_OFFS[l + 1] * DIM, H_SIZES[l], H_SIZES[l + 1]);
    }
    for (int l = 2; l < 6; l++) {
        int Ml = H_SIZES[l], M1 = H_SIZES[l + 1];
        const float* Xc = (l == 5) ? leaf_agg : (p_agg + (size_t)H_OFFS[l + 1] * DIM);

        gemm_relu_big<<<(Ml + 255) / 256, 256, SMEM_BIG>>>(
            p_ctx + (size_t)H_OFFS[l] * DIM, Wx, bx, p_t2, Ml);
        down_combine_big<<<(M1 + 255) / 256, 256, SMEM_BIG>>>(
            Xc, Wx, bx, p_t2,
            p_ctx + (size_t)H_OFFS[l + 1] * DIM, M1);
    }

    // ---- final ----
    final_big<<<(N_TOTAL + 255) / 256, 256, SMEM_BIG>>>(
        p_ctx, p_agg, initial, NTOP,
        Wf, bf, Wh, bh, out, N_TOTAL);
}

// round 6
// speedup vs baseline: 1.3610x; 1.0157x over previous
#include <cuda_runtime.h>
#include <cuda_bf16.h>

#define DIM 128
#define N_TOTAL 299593
#define NTOP 37449

static const int H_SIZES[7] = {1, 8, 64, 512, 4096, 32768, 262144};
static const int H_OFFS[8]  = {0, 1, 9, 73, 585, 4681, 37449, 299593};

// ---------------- scratch ----------------
__device__ float g_agg[NTOP * DIM];
__device__ float g_ctx[N_TOTAL * DIM];
__device__ float g_t2 [65536 * DIM];

// ================= bf16x3 tensor-core GEMM machinery =================
#define SPITCH 136
#define STILE  (128 * SPITCH)
#define XTILE  (256 * SPITCH)
#define EPITCH 132

__device__ __forceinline__ void mma16816(float* c, const unsigned* a,
                                         unsigned b0, unsigned b1)
{
    asm volatile(
        "mma.sync.aligned.m16n8k16.row.col.f32.bf16.bf16.f32 "
        "{%0,%1,%2,%3},{%4,%5,%6,%7},{%8,%9},{%0,%1,%2,%3};\n"
        : "+f"(c[0]), "+f"(c[1]), "+f"(c[2]), "+f"(c[3])
        : "r"(a[0]), "r"(a[1]), "r"(a[2]), "r"(a[3]), "r"(b0), "r"(b1));
}

__device__ __forceinline__ void ldsm4(unsigned* r, unsigned addr)
{
    asm volatile("ldmatrix.sync.aligned.m8n8.x4.shared.b16 {%0,%1,%2,%3}, [%4];"
                 : "=r"(r[0]), "=r"(r[1]), "=r"(r[2]), "=r"(r[3]) : "r"(addr));
}

// Stage an nrows x 128 fp32 tile into bf16 hi/lo smem tiles (pitch SPITCH).
__device__ __forceinline__ void stage_tile(
    const float* __restrict__ G, int nrows, int rows_valid, int gstride,
    __nv_bfloat16* shi, __nv_bfloat16* slo, int tid)
{
    for (int idx = tid; idx < nrows * 32; idx += 256) {
        int r = idx >> 5, c4 = (idx & 31) * 4;
        float4 v = make_float4(0.f, 0.f, 0.f, 0.f);
        if (r < rows_valid) v = *(const float4*)(G + (size_t)r * gstride + c4);

        __nv_bfloat16 h0 = __float2bfloat16(v.x);
        __nv_bfloat16 h1 = __float2bfloat16(v.y);
        __nv_bfloat16 h2 = __float2bfloat16(v.z);
        __nv_bfloat16 h3 = __float2bfloat16(v.w);
        __nv_bfloat16 l0 = __float2bfloat16(v.x - __bfloat162float(h0));
        __nv_bfloat16 l1 = __float2bfloat16(v.y - __bfloat162float(h1));
        __nv_bfloat16 l2 = __float2bfloat16(v.z - __bfloat162float(h2));
        __nv_bfloat16 l3 = __float2bfloat16(v.w - __bfloat162float(h3));

        uint2 hv, lv;
        hv.x = ((unsigned)__bfloat16_as_ushort(h1) << 16) | __bfloat16_as_ushort(h0);
        hv.y = ((unsigned)__bfloat16_as_ushort(h3) << 16) | __bfloat16_as_ushort(h2);
        lv.x = ((unsigned)__bfloat16_as_ushort(l1) << 16) | __bfloat16_as_ushort(l0);
        lv.y = ((unsigned)__bfloat16_as_ushort(l3) << 16) | __bfloat16_as_ushort(l2);
        *(uint2*)(shi + (size_t)r * SPITCH + c4) = hv;
        *(uint2*)(slo + (size_t)r * SPITCH + c4) = lv;
    }
}

// 256-row stage with per-row source select (row<bnd -> A else B, stride 128).
__device__ __forceinline__ void stage_tile_sel(
    const float* __restrict__ A, const float* __restrict__ B, int bnd,
    int grow0, int M, __nv_bfloat16* shi, __nv_bfloat16* slo, int tid)
{
    for (int idx = tid; idx < 256 * 32; idx += 256) {
        int r = idx >> 5, c4 = (idx & 31) * 4;
        int gr = grow0 + r;
        float4 v = make_float4(0.f, 0.f, 0.f, 0.f);
        if (gr < M) {
            const float* src = (gr < bnd) ? A : B;
            v = *(const float4*)(src + (size_t)gr * 128 + c4);
        }
        __nv_bfloat16 h0 = __float2bfloat16(v.x);
        __nv_bfloat16 h1 = __float2bfloat16(v.y);
        __nv_bfloat16 h2 = __float2bfloat16(v.z);
        __nv_bfloat16 h3 = __float2bfloat16(v.w);
        __nv_bfloat16 l0 = __float2bfloat16(v.x - __bfloat162float(h0));
        __nv_bfloat16 l1 = __float2bfloat16(v.y - __bfloat162float(h1));
        __nv_bfloat16 l2 = __float2bfloat16(v.z - __bfloat162float(h2));
        __nv_bfloat16 l3 = __float2bfloat16(v.w - __bfloat162float(h3));
        uint2 hv, lv;
        hv.x = ((unsigned)__bfloat16_as_ushort(h1) << 16) | __bfloat16_as_ushort(h0);
        hv.y = ((unsigned)__bfloat16_as_ushort(h3) << 16) | __bfloat16_as_ushort(h2);
        lv.x = ((unsigned)__bfloat16_as_ushort(l1) << 16) | __bfloat16_as_ushort(l0);
        lv.y = ((unsigned)__bfloat16_as_ushort(l3) << 16) | __bfloat16_as_ushort(l2);
        *(uint2*)(shi + (size_t)r * SPITCH + c4) = hv;
        *(uint2*)(slo + (size_t)r * SPITCH + c4) = lv;
    }
}

// ---- mainloop v2: ldmatrix + accumulator-independent ordering ----
// Per k-chunk: 3 passes (hi*hi, hi*lo, lo*hi); B-hi fragments held in regs
// across passes 1 and 3. Consecutive MMAs always hit different accumulators.

// 256-row variant (2 m16 row-tiles per warp).
__device__ __forceinline__ void panel_mma2_v2(
    const __nv_bfloat16* sWhi, const __nv_bfloat16* sWlo,
    const __nv_bfloat16* sXhi, const __nv_bfloat16* sXlo,
    int warp, int lane, float C[2][16][4])
{
    const unsigned wh = (unsigned)__cvta_generic_to_shared(sWhi);
    const unsigned wl = (unsigned)__cvta_generic_to_shared(sWlo);
    const unsigned xh = (unsigned)__cvta_generic_to_shared(sXhi);
    const unsigned xl = (unsigned)__cvta_generic_to_shared(sXlo);
    const unsigned PB = SPITCH * 2;
    const unsigned aoff0 = (unsigned)(warp * 32 + (lane & 15)) * PB
                         + (unsigned)((lane >> 4) & 1) * 16u;
    const unsigned boff0 = (unsigned)((lane & 7) + ((lane & 16) >> 1)) * PB
                         + ((lane & 8) ? 16u : 0u);

    for (int kc = 0; kc < 8; kc++) {
        const unsigned ka = kc * 32;
        unsigned ah0[4], ah1[4], al0[4], al1[4];
        ldsm4(ah0, xh + aoff0 + ka);
        ldsm4(ah1, xh + aoff0 + 16 * PB + ka);
        ldsm4(al0, xl + aoff0 + ka);
        ldsm4(al1, xl + aoff0 + 16 * PB + ka);

        unsigned bhi[8][4];
#pragma unroll
        for (int p = 0; p < 8; p++)
            ldsm4(bhi[p], wh + boff0 + (unsigned)p * 16 * PB + ka);
#pragma unroll
        for (int p = 0; p < 8; p++) {
            mma16816(C[0][2 * p],     ah0, bhi[p][0], bhi[p][1]);
            mma16816(C[1][2 * p],     ah1, bhi[p][0], bhi[p][1]);
            mma16816(C[0][2 * p + 1], ah0, bhi[p][2], bhi[p][3]);
            mma16816(C[1][2 * p + 1], ah1, bhi[p][2], bhi[p][3]);
        }
#pragma unroll
        for (int p = 0; p < 8; p++) {
            unsigned bl[4];
            ldsm4(bl, wl + boff0 + (unsigned)p * 16 * PB + ka);
            mma16816(C[0][2 * p],     ah0, bl[0], bl[1]);
            mma16816(C[1][2 * p],     ah1, bl[0], bl[1]);
            mma16816(C[0][2 * p + 1], ah0, bl[2], bl[3]);
            mma16816(C[1][2 * p + 1], ah1, bl[2], bl[3]);
        }
#pragma unroll
        for (int p = 0; p < 8; p++) {
            mma16816(C[0][2 * p],     al0, bhi[p][0], bhi[p][1]);
            mma16816(C[1][2 * p],     al1, bhi[p][0], bhi[p][1]);
            mma16816(C[0][2 * p + 1], al0, bhi[p][2], bhi[p][3]);
            mma16816(C[1][2 * p + 1], al1, bhi[p][2], bhi[p][3]);
        }
    }
}

// 128-row variant (1 m16 row-tile per warp).
__device__ __forceinline__ void panel_mma1_v2(
    const __nv_bfloat16* sWhi, const __nv_bfloat16* sWlo,
    const __nv_bfloat16* sXhi, const __nv_bfloat16* sXlo,
    int warp, int lane, float C[16][4])
{
    const unsigned wh = (unsigned)__cvta_generic_to_shared(sWhi);
    const unsigned wl = (unsigned)__cvta_generic_to_shared(sWlo);
    const unsigned xh = (unsigned)__cvta_generic_to_shared(sXhi);
    const unsigned xl = (unsigned)__cvta_generic_to_shared(sXlo);
    const unsigned PB = SPITCH * 2;
    const unsigned aoff0 = (unsigned)(warp * 16 + (lane & 15)) * PB
                         + (unsigned)((lane >> 4) & 1) * 16u;
    const unsigned boff0 = (unsigned)((lane & 7) + ((lane & 16) >> 1)) * PB
                         + ((lane & 8) ? 16u : 0u);

    for (int kc = 0; kc < 8; kc++) {
        const unsigned ka = kc * 32;
        unsigned ah[4], al[4];
        ldsm4(ah, xh + aoff0 + ka);
        ldsm4(al, xl + aoff0 + ka);

        unsigned bhi[8][4];
#pragma unroll
        for (int p = 0; p < 8; p++)
            ldsm4(bhi[p], wh + boff0 + (unsigned)p * 16 * PB + ka);
#pragma unroll
        for (int p = 0; p < 8; p++) {
            mma16816(C[2 * p],     ah, bhi[p][0], bhi[p][1]);
            mma16816(C[2 * p + 1], ah, bhi[p][2], bhi[p][3]);
        }
#pragma unroll
        for (int p = 0; p < 8; p++) {
            unsigned bl[4];
            ldsm4(bl, wl + boff0 + (unsigned)p * 16 * PB + ka);
            mma16816(C[2 * p],     ah, bl[0], bl[1]);
            mma16816(C[2 * p + 1], ah, bl[2], bl[3]);
        }
#pragma unroll
        for (int p = 0; p < 8; p++) {
            mma16816(C[2 * p],     al, bhi[p][0], bhi[p][1]);
            mma16816(C[2 * p + 1], al, bhi[p][2], bhi[p][3]);
        }
    }
}

__device__ __forceinline__ void zero_C(float C[16][4])
{
#pragma unroll
    for (int t = 0; t < 16; t++) C[t][0] = C[t][1] = C[t][2] = C[t][3] = 0.f;
}

__device__ __forceinline__ void epilogue_to_smem(
    const float C[16][4], const float* __restrict__ bias,
    float* sE, int warp, int g, int tg)
{
    const int r0 = warp * 16 + g, r1 = r0 + 8;
#pragma unroll
    for (int t = 0; t < 16; t++) {
        int c = t * 8 + tg * 2;
        float2 bv = *(const float2*)(bias + c);
        sE[r0 * EPITCH + c]     = fmaxf(C[t][0] + bv.x, 0.f);
        sE[r0 * EPITCH + c + 1] = fmaxf(C[t][1] + bv.y, 0.f);
        sE[r1 * EPITCH + c]     = fmaxf(C[t][2] + bv.x, 0.f);
        sE[r1 * EPITCH + c + 1] = fmaxf(C[t][3] + bv.y, 0.f);
    }
}

__device__ __forceinline__ void epilogue_to_smem2(
    const float C[2][16][4], const float* __restrict__ bias,
    float* sE, int warp, int g, int tg)
{
#pragma unroll
    for (int rt = 0; rt < 2; rt++) {
        const int r0 = warp * 32 + rt * 16 + g, r1 = r0 + 8;
#pragma unroll
        for (int t = 0; t < 16; t++) {
            int c = t * 8 + tg * 2;
            float2 bv = *(const float2*)(bias + c);
            sE[r0 * EPITCH + c]     = fmaxf(C[rt][t][0] + bv.x, 0.f);
            sE[r0 * EPITCH + c + 1] = fmaxf(C[rt][t][1] + bv.y, 0.f);
            sE[r1 * EPITCH + c]     = fmaxf(C[rt][t][2] + bv.x, 0.f);
            sE[r1 * EPITCH + c + 1] = fmaxf(C[rt][t][3] + bv.y, 0.f);
        }
    }
}

__device__ __forceinline__ void mean4_red(
    const float* sE, float* __restrict__ T2, int og0, int G, int nrows, int tid)
{
    int col = tid & 127;
    for (int q = tid >> 7; q < (nrows >> 2); q += 2) {
        int og = og0 + q;
        if (og < G) {
            float v = sE[(4 * q) * EPITCH + col] + sE[(4 * q + 1) * EPITCH + col]
                    + sE[(4 * q + 2) * EPITCH + col] + sE[(4 * q + 3) * EPITCH + col];
            T2[(size_t)og * 128 + col] = 0.25f * v;
        }
    }
}

__device__ __forceinline__ void pairadd_red(
    const float* sE, const float* __restrict__ init, float* __restrict__ OUT,
    int og0, int Mout, int nrows, int tid)
{
    int col = tid & 127;
    for (int q = tid >> 7; q < (nrows >> 1); q += 2) {
        int og = og0 + q;
        if (og < Mout) {
            float v = sE[(2 * q) * EPITCH + col] + sE[(2 * q + 1) * EPITCH + col];
            OUT[(size_t)og * 128 + col] = init[(size_t)og * 128 + col] + 0.5f * v;
        }
    }
}

__device__ __forceinline__ void combine_red(
    const float* sE, const float* __restrict__ CTH, float* __restrict__ OUT,
    int row0, int M1, int nrows, int tid)
{
    int col = tid & 127;
    for (int q = tid >> 7; q < (nrows >> 2); q += 2) {
        int base = row0 + 4 * q;
        if (base < M1) {
            float s = sE[(4 * q) * EPITCH + col] + sE[(4 * q + 1) * EPITCH + col]
                    + sE[(4 * q + 2) * EPITCH + col] + sE[(4 * q + 3) * EPITCH + col];
            float tot = CTH[(size_t)(base >> 3) * 128 + col] + s;
#pragma unroll
            for (int s4 = 0; s4 < 4; s4++)
                OUT[(size_t)(base + s4) * 128 + col] =
                    0.25f * (tot - sE[(4 * q + s4) * EPITCH + col]);
        }
    }
}

// ================= big-level kernels (256-row tiles) =================
#define SMEM_BIG ((2 * STILE + 2 * XTILE) * (int)sizeof(__nv_bfloat16))

__global__ void __launch_bounds__(256, 1) gemm_relu_big(
    const float* __restrict__ X, const float* __restrict__ W,
    const float* __restrict__ bias, float* __restrict__ Y, int M)
{
    extern __shared__ __nv_bfloat16 sm[];
    __nv_bfloat16 *sWhi = sm, *sWlo = sm + STILE;
    __nv_bfloat16 *sXhi = sm + 2 * STILE, *sXlo = sm + 2 * STILE + XTILE;
    const int tid = threadIdx.x, lane = tid & 31, warp = tid >> 5;
    const int g = lane >> 2, tg = lane & 3;
    const int row0 = blockIdx.x * 256;

    stage_tile(W, 128, 128, 128, sWhi, sWlo, tid);
    stage_tile(X + (size_t)row0 * 128, 256, M - row0, 128, sXhi, sXlo, tid);
    __syncthreads();
    float C[2][16][4]; zero_C(C[0]); zero_C(C[1]);
    panel_mma2_v2(sWhi, sWlo, sXhi, sXlo, warp, lane, C);

#pragma unroll
    for (int rt = 0; rt < 2; rt++) {
        const int r0 = row0 + warp * 32 + rt * 16 + g, r1 = r0 + 8;
#pragma unroll
        for (int t = 0; t < 16; t++) {
            int c = t * 8 + tg * 2;
            float2 bv = *(const float2*)(bias + c);
            if (r0 < M) *(float2*)(Y + (size_t)r0 * 128 + c) =
                make_float2(fmaxf(C[rt][t][0] + bv.x, 0.f), fmaxf(C[rt][t][1] + bv.y, 0.f));
            if (r1 < M) *(float2*)(Y + (size_t)r1 * 128 + c) =
                make_float2(fmaxf(C[rt][t][2] + bv.x, 0.f), fmaxf(C[rt][t][3] + bv.y, 0.f));
        }
    }
}

__global__ void __launch_bounds__(256, 1) up_mean4_big(
    const float* __restrict__ X, const float* __restrict__ W,
    const float* __restrict__ bias, float* __restrict__ T2, int M1)
{
    extern __shared__ __nv_bfloat16 sm[];
    __nv_bfloat16 *sWhi = sm, *sWlo = sm + STILE;
    __nv_bfloat16 *sXhi = sm + 2 * STILE, *sXlo = sm + 2 * STILE + XTILE;
    float* sE = (float*)(sm + 2 * STILE);
    const int tid = threadIdx.x, lane = tid & 31, warp = tid >> 5;
    const int g = lane >> 2, tg = lane & 3;
    const int row0 = blockIdx.x * 256;

    stage_tile(W, 128, 128, 128, sWhi, sWlo, tid);
    stage_tile(X + (size_t)row0 * 128, 256, M1 - row0, 128, sXhi, sXlo, tid);
    __syncthreads();
    float C[2][16][4]; zero_C(C[0]); zero_C(C[1]);
    panel_mma2_v2(sWhi, sWlo, sXhi, sXlo, warp, lane, C);
    __syncthreads();
    epilogue_to_smem2(C, bias, sE, warp, g, tg);
    __syncthreads();
    mean4_red(sE, T2, row0 >> 2, M1 >> 2, 256, tid);
}

__global__ void __launch_bounds__(256, 1) up_pairadd_big(
    const float* __restrict__ X, const float* __restrict__ W,
    const float* __restrict__ bias, const float* __restrict__ init,
    float* __restrict__ AGG, int G)
{
    extern __shared__ __nv_bfloat16 sm[];
    __nv_bfloat16 *sWhi = sm, *sWlo = sm + STILE;
    __nv_bfloat16 *sXhi = sm + 2 * STILE, *sXlo = sm + 2 * STILE + XTILE;
    float* sE = (float*)(sm + 2 * STILE);
    const int tid = threadIdx.x, lane = tid & 31, warp = tid >> 5;
    const int g = lane >> 2, tg = lane & 3;
    const int row0 = blockIdx.x * 256;

    stage_tile(W, 128, 128, 128, sWhi, sWlo, tid);
    stage_tile(X + (size_t)row0 * 128, 256, G - row0, 128, sXhi, sXlo, tid);
    __syncthreads();
    float C[2][16][4]; zero_C(C[0]); zero_C(C[1]);
    panel_mma2_v2(sWhi, sWlo, sXhi, sXlo, warp, lane, C);
    __syncthreads();
    epilogue_to_smem2(C, bias, sE, warp, g, tg);
    __syncthreads();
    pairadd_red(sE, init, AGG, row0 >> 1, G >> 1, 256, tid);
}

__global__ void __launch_bounds__(256, 1) down_combine_big(
    const float* __restrict__ X, const float* __restrict__ W,
    const float* __restrict__ bias, const float* __restrict__ CTH,
    float* __restrict__ OUT, int M1)
{
    extern __shared__ __nv_bfloat16 sm[];
    __nv_bfloat16 *sWhi = sm, *sWlo = sm + STILE;
    __nv_bfloat16 *sXhi = sm + 2 * STILE, *sXlo = sm + 2 * STILE + XTILE;
    float* sE = (float*)(sm + 2 * STILE);
    const int tid = threadIdx.x, lane = tid & 31, warp = tid >> 5;
    const int g = lane >> 2, tg = lane & 3;
    const int row0 = blockIdx.x * 256;

    stage_tile(W, 128, 128, 128, sWhi, sWlo, tid);
    stage_tile(X + (size_t)row0 * 128, 256, M1 - row0, 128, sXhi, sXlo, tid);
    __syncthreads();
    float C[2][16][4]; zero_C(C[0]); zero_C(C[1]);
    panel_mma2_v2(sWhi, sWlo, sXhi, sXlo, warp, lane, C);
    __syncthreads();
    epilogue_to_smem2(C, bias, sE, warp, g, tg);
    __syncthreads();
    combine_red(sE, CTH, OUT, row0, M1, 256, tid);
}

__global__ void __launch_bounds__(256, 1) final_big(
    const float* __restrict__ CTX,
    const float* __restrict__ AGGa, const float* __restrict__ AGGb, int bnd,
    const float* __restrict__ Wf, const float* __restrict__ bf,
    const float* __restrict__ Wh, const float* __restrict__ bh,
    float* __restrict__ out, int M)
{
    extern __shared__ __nv_bfloat16 sm[];
    __nv_bfloat16 *sWhi = sm, *sWlo = sm + STILE;
    __nv_bfloat16 *sXhi = sm + 2 * STILE, *sXlo = sm + 2 * STILE + XTILE;
    const int tid = threadIdx.x, lane = tid & 31, warp = tid >> 5;
    const int g = lane >> 2, tg = lane & 3;
    const int row0 = blockIdx.x * 256;

    float C[2][16][4]; zero_C(C[0]); zero_C(C[1]);
    for (int p = 0; p < 2; p++) {
        __syncthreads();
        stage_tile(Wf + p * 128, 128, 128, 256, sWhi, sWlo, tid);
        if (p == 0)
            stage_tile(CTX + (size_t)row0 * 128, 256, M - row0, 128, sXhi, sXlo, tid);
        else
            stage_tile_sel(AGGa, AGGb, bnd, row0, M, sXhi, sXlo, tid);
        __syncthreads();
        panel_mma2_v2(sWhi, sWlo, sXhi, sXlo, warp, lane, C);
    }

#pragma unroll
    for (int rt = 0; rt < 2; rt++) {
        float s0 = 0.f, s1 = 0.f;
#pragma unroll
        for (int t = 0; t < 16; t++) {
            int c = t * 8 + tg * 2;
            float2 bv = *(const float2*)(bf + c);
            float2 wv = *(const float2*)(Wh + c);
            s0 += fmaxf(C[rt][t][0] + bv.x, 0.f) * wv.x + fmaxf(C[rt][t][1] + bv.y, 0.f) * wv.y;
            s1 += fmaxf(C[rt][t][2] + bv.x, 0.f) * wv.x + fmaxf(C[rt][t][3] + bv.y, 0.f) * wv.y;
        }
        s0 += __shfl_xor_sync(0xffffffffu, s0, 1);
        s0 += __shfl_xor_sync(0xffffffffu, s0, 2);
        s1 += __shfl_xor_sync(0xffffffffu, s1, 1);
        s1 += __shfl_xor_sync(0xffffffffu, s1, 2);
        if (tg == 0) {
            const int r0 = row0 + warp * 32 + rt * 16 + g, r1 = r0 + 8;
            float bhv = bh[0];
            if (r0 < M) out[r0] = s0 + bhv;
            if (r1 < M) out[r1] = s1 + bhv;
        }
    }
}

// ================= tiny-level kernels (single block, 128-row machinery) =================
#define SMEM_SMALL (4 * STILE * (int)sizeof(__nv_bfloat16))

__global__ void __launch_bounds__(256) up_small(
    const float* __restrict__ Xc, const float* __restrict__ init_l,
    float* __restrict__ AGG,
    const float* __restrict__ Ws, const float* __restrict__ bs,
    const float* __restrict__ Wc, const float* __restrict__ bc,
    float* __restrict__ T2, int M1)
{
    extern __shared__ __nv_bfloat16 sm[];
    __nv_bfloat16 *sWhi = sm, *sWlo = sm + STILE, *sXhi = sm + 2 * STILE, *sXlo = sm + 3 * STILE;
    float* sE = (float*)(sm + 2 * STILE);
    const int tid = threadIdx.x, lane = tid & 31, warp = tid >> 5;
    const int g = lane >> 2, tg = lane & 3;
    const int G = M1 >> 2, Mout = M1 >> 3;

    stage_tile(Ws, 128, 128, 128, sWhi, sWlo, tid);
    stage_tile(Xc, 128, M1, 128, sXhi, sXlo, tid);
    __syncthreads();
    {
        float C[16][4]; zero_C(C);
        panel_mma1_v2(sWhi, sWlo, sXhi, sXlo, warp, lane, C);
        __syncthreads();
        epilogue_to_smem(C, bs, sE, warp, g, tg);
        __syncthreads();
        mean4_red(sE, T2, 0, G, 128, tid);
    }
    __syncthreads();
    stage_tile(Wc, 128, 128, 128, sWhi, sWlo, tid);
    stage_tile(T2, 128, G, 128, sXhi, sXlo, tid);
    __syncthreads();
    {
        float C[16][4]; zero_C(C);
        panel_mma1_v2(sWhi, sWlo, sXhi, sXlo, warp, lane, C);
        __syncthreads();
        epilogue_to_smem(C, bc, sE, warp, g, tg);
        __syncthreads();
        pairadd_red(sE, init_l, AGG, 0, Mout, 128, tid);
    }
}

__global__ void __launch_bounds__(256) down_small(
    const float* __restrict__ ctx_l, const float* __restrict__ aggc,
    const float* __restrict__ Wx, const float* __restrict__ bx,
    float* __restrict__ T2, float* __restrict__ ctx_out, int Ml, int M1)
{
    extern __shared__ __nv_bfloat16 sm[];
    __nv_bfloat16 *sWhi = sm, *sWlo = sm + STILE, *sXhi = sm + 2 * STILE, *sXlo = sm + 3 * STILE;
    float* sE = (float*)(sm + 2 * STILE);
    const int tid = threadIdx.x, lane = tid & 31, warp = tid >> 5;
    const int g = lane >> 2, tg = lane & 3;

    stage_tile(Wx, 128, 128, 128, sWhi, sWlo, tid);
    stage_tile(ctx_l, 128, Ml, 128, sXhi, sXlo, tid);
    __syncthreads();
    {
        float C[16][4]; zero_C(C);
        panel_mma1_v2(sWhi, sWlo, sXhi, sXlo, warp, lane, C);
        const int r0 = warp * 16 + g, r1 = r0 + 8;
#pragma unroll
        for (int t = 0; t < 16; t++) {
            int c = t * 8 + tg * 2;
            float2 bv = *(const float2*)(bx + c);
            if (r0 < Ml) *(float2*)(T2 + (size_t)r0 * 128 + c) =
                make_float2(fmaxf(C[t][0] + bv.x, 0.f), fmaxf(C[t][1] + bv.y, 0.f));
            if (r1 < Ml) *(float2*)(T2 + (size_t)r1 * 128 + c) =
                make_float2(fmaxf(C[t][2] + bv.x, 0.f), fmaxf(C[t][3] + bv.y, 0.f));
        }
    }
    __syncthreads();
    stage_tile(aggc, 128, M1, 128, sXhi, sXlo, tid);
    __syncthreads();
    {
        float C[16][4]; zero_C(C);
        panel_mma1_v2(sWhi, sWlo, sXhi, sXlo, warp, lane, C);
        __syncthreads();
        epilogue_to_smem(C, bx, sE, warp, g, tg);
        __syncthreads();
        combine_red(sE, T2, ctx_out, 0, M1, 128, tid);
    }
}

__global__ void set_ones(float* p, int n)
{
    int i = blockIdx.x * blockDim.x + threadIdx.x;
    if (i < n) p[i] = 1.0f;
}

// ---------------- launch ----------------
extern "C" void kernel_launch(void* const* d_in, const int* in_sizes, int n_in,
                              void* d_out, int out_size)
{
    const float* initial = (const float*)d_in[0];
    const float* Ws = (const float*)d_in[1];
    const float* bs = (const float*)d_in[2];
    const float* Wc = (const float*)d_in[3];
    const float* bc = (const float*)d_in[4];
    const float* Wx = (const float*)d_in[5];
    const float* bx = (const float*)d_in[6];
    const float* Wf = (const float*)d_in[7];
    const float* bf = (const float*)d_in[8];
    const float* Wh = (const float*)d_in[9];
    const float* bh = (const float*)d_in[10];
    float* out = (float*)d_out;

    float *p_agg, *p_ctx, *p_t2;
    cudaGetSymbolAddress((void**)&p_agg, g_agg);
    cudaGetSymbolAddress((void**)&p_ctx, g_ctx);
    cudaGetSymbolAddress((void**)&p_t2,  g_t2);

    cudaFuncSetAttribute(gemm_relu_big,    cudaFuncAttributeMaxDynamicSharedMemorySize, SMEM_BIG);
    cudaFuncSetAttribute(up_mean4_big,     cudaFuncAttributeMaxDynamicSharedMemorySize, SMEM_BIG);
    cudaFuncSetAttribute(up_pairadd_big,   cudaFuncAttributeMaxDynamicSharedMemorySize, SMEM_BIG);
    cudaFuncSetAttribute(down_combine_big, cudaFuncAttributeMaxDynamicSharedMemorySize, SMEM_BIG);
    cudaFuncSetAttribute(final_big,        cudaFuncAttributeMaxDynamicSharedMemorySize, SMEM_BIG);
    cudaFuncSetAttribute(up_small,         cudaFuncAttributeMaxDynamicSharedMemorySize, SMEM_SMALL);
    cudaFuncSetAttribute(down_small,       cudaFuncAttributeMaxDynamicSharedMemorySize, SMEM_SMALL);

    const float* leaf_agg = initial + (size_t)H_OFFS[6] * DIM;

    // ---- up pass: levels 5..2 (2 parallel launches each) ----
    for (int l = 5; l >= 2; l--) {
        int M1 = H_SIZES[l + 1];
        int G  = M1 >> 2;
        const float* Xc = (l == 5) ? leaf_agg : (p_agg + (size_t)H_OFFS[l + 1] * DIM);

        up_mean4_big<<<(M1 + 255) / 256, 256, SMEM_BIG>>>(Xc, Ws, bs, p_t2, M1);
        up_pairadd_big<<<(G + 255) / 256, 256, SMEM_BIG>>>(
            p_t2, Wc, bc,
            initial + (size_t)H_OFFS[l] * DIM,
            p_agg + (size_t)H_OFFS[l] * DIM, G);
    }
    for (int l = 1; l >= 0; l--) {
        up_small<<<1, 256, SMEM_SMALL>>>(
            p_agg + (size_t)H_OFFS[l + 1] * DIM,
            initial + (size_t)H_OFFS[l] * DIM,
            p_agg + (size_t)H_OFFS[l] * DIM,
            Ws, bs, Wc, bc, p_t2, H_SIZES[l + 1]);
    }

    // ---- down pass ----
    set_ones<<<1, 128>>>(p_ctx, DIM);
    for (int l = 0; l < 2; l++) {
        down_small<<<1, 256, SMEM_SMALL>>>(
            p_ctx + (size_t)H_OFFS[l] * DIM,
            p_agg + (size_t)H_OFFS[l + 1] * DIM,
            Wx, bx, p_t2,
            p_ctx + (size_t)H_OFFS[l + 1] * DIM, H_SIZES[l], H_SIZES[l + 1]);
    }
    for (int l = 2; l < 6; l++) {
        int Ml = H_SIZES[l], M1 = H_SIZES[l + 1];
        const float* Xc = (l == 5) ? leaf_agg : (p_agg + (size_t)H_OFFS[l + 1] * DIM);

        gemm_relu_big<<<(Ml + 255) / 256, 256, SMEM_BIG>>>(
            p_ctx + (size_t)H_OFFS[l] * DIM, Wx, bx, p_t2, Ml);
        down_combine_big<<<(M1 + 255) / 256, 256, SMEM_BIG>>>(
            Xc, Wx, bx, p_t2,
            p_ctx + (size_t)H_OFFS[l + 1] * DIM, M1);
    }

    // ---- final ----
    final_big<<<(N_TOTAL + 255) / 256, 256, SMEM_BIG>>>(
        p_ctx, p_agg, initial, NTOP,
        Wf, bf, Wh, bh, out, N_TOTAL);
}

// round 7
// speedup vs baseline: 1.6394x; 1.2046x over previous
#include <cuda_runtime.h>
#include <cuda_bf16.h>

#define DIM 128
#define N_TOTAL 299593
#define NTOP 37449

static const int H_SIZES[7] = {1, 8, 64, 512, 4096, 32768, 262144};
static const int H_OFFS[8]  = {0, 1, 9, 73, 585, 4681, 37449, 299593};

// ---------------- scratch ----------------
__device__ float g_agg[NTOP * DIM];
__device__ float g_ctx[N_TOTAL * DIM];
__device__ float g_t2 [65536 * DIM];

// ================= bf16x3 tensor-core GEMM machinery =================
#define SPITCH 136
#define STILE  (128 * SPITCH)
#define XTILE  (256 * SPITCH)
#define EPITCH 132

__device__ __forceinline__ void mma16816(float* c, const unsigned* a,
                                         unsigned b0, unsigned b1)
{
    asm volatile(
        "mma.sync.aligned.m16n8k16.row.col.f32.bf16.bf16.f32 "
        "{%0,%1,%2,%3},{%4,%5,%6,%7},{%8,%9},{%0,%1,%2,%3};\n"
        : "+f"(c[0]), "+f"(c[1]), "+f"(c[2]), "+f"(c[3])
        : "r"(a[0]), "r"(a[1]), "r"(a[2]), "r"(a[3]), "r"(b0), "r"(b1));
}

__device__ __forceinline__ void ldsm4(unsigned* r, unsigned addr)
{
    asm volatile("ldmatrix.sync.aligned.m8n8.x4.shared.b16 {%0,%1,%2,%3}, [%4];"
                 : "=r"(r[0]), "=r"(r[1]), "=r"(r[2]), "=r"(r[3]) : "r"(addr));
}

__device__ __forceinline__ void cvt_store(
    float4 v, __nv_bfloat16* shi, __nv_bfloat16* slo, int r, int c4)
{
    __nv_bfloat16 h0 = __float2bfloat16(v.x);
    __nv_bfloat16 h1 = __float2bfloat16(v.y);
    __nv_bfloat16 h2 = __float2bfloat16(v.z);
    __nv_bfloat16 h3 = __float2bfloat16(v.w);
    __nv_bfloat16 l0 = __float2bfloat16(v.x - __bfloat162float(h0));
    __nv_bfloat16 l1 = __float2bfloat16(v.y - __bfloat162float(h1));
    __nv_bfloat16 l2 = __float2bfloat16(v.z - __bfloat162float(h2));
    __nv_bfloat16 l3 = __float2bfloat16(v.w - __bfloat162float(h3));
    uint2 hv, lv;
    hv.x = ((unsigned)__bfloat16_as_ushort(h1) << 16) | __bfloat16_as_ushort(h0);
    hv.y = ((unsigned)__bfloat16_as_ushort(h3) << 16) | __bfloat16_as_ushort(h2);
    lv.x = ((unsigned)__bfloat16_as_ushort(l1) << 16) | __bfloat16_as_ushort(l0);
    lv.y = ((unsigned)__bfloat16_as_ushort(l3) << 16) | __bfloat16_as_ushort(l2);
    *(uint2*)(shi + (size_t)r * SPITCH + c4) = hv;
    *(uint2*)(slo + (size_t)r * SPITCH + c4) = lv;
}

// Stage NROWS x 128 fp32 tile into bf16 hi/lo smem. Batched loads -> MLP ~16.
template <int NROWS>
__device__ __forceinline__ void stage_tile(
    const float* __restrict__ G, int rows_valid, int gstride,
    __nv_bfloat16* shi, __nv_bfloat16* slo, int tid)
{
    constexpr int ITERS = NROWS * 32 / 256;      // 16 (128 rows) or 32 (256 rows)
    constexpr int BATCH = 16;
#pragma unroll
    for (int b = 0; b < ITERS; b += BATCH) {
        float4 v[BATCH];
#pragma unroll
        for (int j = 0; j < BATCH; j++) {
            int idx = tid + (b + j) * 256;
            int r = idx >> 5, c4 = (idx & 31) * 4;
            v[j] = make_float4(0.f, 0.f, 0.f, 0.f);
            if (r < rows_valid) v[j] = *(const float4*)(G + (size_t)r * gstride + c4);
        }
#pragma unroll
        for (int j = 0; j < BATCH; j++) {
            int idx = tid + (b + j) * 256;
            cvt_store(v[j], shi, slo, idx >> 5, (idx & 31) * 4);
        }
    }
}

// 256-row stage with per-row source select (row<bnd -> A else B, stride 128).
__device__ __forceinline__ void stage_tile_sel(
    const float* __restrict__ A, const float* __restrict__ B, int bnd,
    int grow0, int M, __nv_bfloat16* shi, __nv_bfloat16* slo, int tid)
{
    constexpr int ITERS = 32;
    constexpr int BATCH = 16;
#pragma unroll
    for (int b = 0; b < ITERS; b += BATCH) {
        float4 v[BATCH];
#pragma unroll
        for (int j = 0; j < BATCH; j++) {
            int idx = tid + (b + j) * 256;
            int r = idx >> 5, c4 = (idx & 31) * 4;
            int gr = grow0 + r;
            v[j] = make_float4(0.f, 0.f, 0.f, 0.f);
            if (gr < M) {
                const float* src = (gr < bnd) ? A : B;
                v[j] = *(const float4*)(src + (size_t)gr * 128 + c4);
            }
        }
#pragma unroll
        for (int j = 0; j < BATCH; j++) {
            int idx = tid + (b + j) * 256;
            cvt_store(v[j], shi, slo, idx >> 5, (idx & 31) * 4);
        }
    }
}

// ---- mainloop: ldmatrix + accumulator-independent ordering ----
__device__ __forceinline__ void panel_mma2_v2(
    const __nv_bfloat16* sWhi, const __nv_bfloat16* sWlo,
    const __nv_bfloat16* sXhi, const __nv_bfloat16* sXlo,
    int warp, int lane, float C[2][16][4])
{
    const unsigned wh = (unsigned)__cvta_generic_to_shared(sWhi);
    const unsigned wl = (unsigned)__cvta_generic_to_shared(sWlo);
    const unsigned xh = (unsigned)__cvta_generic_to_shared(sXhi);
    const unsigned xl = (unsigned)__cvta_generic_to_shared(sXlo);
    const unsigned PB = SPITCH * 2;
    const unsigned aoff0 = (unsigned)(warp * 32 + (lane & 15)) * PB
                         + (unsigned)((lane >> 4) & 1) * 16u;
    const unsigned boff0 = (unsigned)((lane & 7) + ((lane & 16) >> 1)) * PB
                         + ((lane & 8) ? 16u : 0u);

    for (int kc = 0; kc < 8; kc++) {
        const unsigned ka = kc * 32;
        unsigned ah0[4], ah1[4], al0[4], al1[4];
        ldsm4(ah0, xh + aoff0 + ka);
        ldsm4(ah1, xh + aoff0 + 16 * PB + ka);
        ldsm4(al0, xl + aoff0 + ka);
        ldsm4(al1, xl + aoff0 + 16 * PB + ka);

        unsigned bhi[8][4];
#pragma unroll
        for (int p = 0; p < 8; p++)
            ldsm4(bhi[p], wh + boff0 + (unsigned)p * 16 * PB + ka);
#pragma unroll
        for (int p = 0; p < 8; p++) {
            mma16816(C[0][2 * p],     ah0, bhi[p][0], bhi[p][1]);
            mma16816(C[1][2 * p],     ah1, bhi[p][0], bhi[p][1]);
            mma16816(C[0][2 * p + 1], ah0, bhi[p][2], bhi[p][3]);
            mma16816(C[1][2 * p + 1], ah1, bhi[p][2], bhi[p][3]);
        }
#pragma unroll
        for (int p = 0; p < 8; p++) {
            unsigned bl[4];
            ldsm4(bl, wl + boff0 + (unsigned)p * 16 * PB + ka);
            mma16816(C[0][2 * p],     ah0, bl[0], bl[1]);
            mma16816(C[1][2 * p],     ah1, bl[0], bl[1]);
            mma16816(C[0][2 * p + 1], ah0, bl[2], bl[3]);
            mma16816(C[1][2 * p + 1], ah1, bl[2], bl[3]);
        }
#pragma unroll
        for (int p = 0; p < 8; p++) {
            mma16816(C[0][2 * p],     al0, bhi[p][0], bhi[p][1]);
            mma16816(C[1][2 * p],     al1, bhi[p][0], bhi[p][1]);
            mma16816(C[0][2 * p + 1], al0, bhi[p][2], bhi[p][3]);
            mma16816(C[1][2 * p + 1], al1, bhi[p][2], bhi[p][3]);
        }
    }
}

__device__ __forceinline__ void panel_mma1_v2(
    const __nv_bfloat16* sWhi, const __nv_bfloat16* sWlo,
    const __nv_bfloat16* sXhi, const __nv_bfloat16* sXlo,
    int warp, int lane, float C[16][4])
{
    const unsigned wh = (unsigned)__cvta_generic_to_shared(sWhi);
    const unsigned wl = (unsigned)__cvta_generic_to_shared(sWlo);
    const unsigned xh = (unsigned)__cvta_generic_to_shared(sXhi);
    const unsigned xl = (unsigned)__cvta_generic_to_shared(sXlo);
    const unsigned PB = SPITCH * 2;
    const unsigned aoff0 = (unsigned)(warp * 16 + (lane & 15)) * PB
                         + (unsigned)((lane >> 4) & 1) * 16u;
    const unsigned boff0 = (unsigned)((lane & 7) + ((lane & 16) >> 1)) * PB
                         + ((lane & 8) ? 16u : 0u);

    for (int kc = 0; kc < 8; kc++) {
        const unsigned ka = kc * 32;
        unsigned ah[4], al[4];
        ldsm4(ah, xh + aoff0 + ka);
        ldsm4(al, xl + aoff0 + ka);

        unsigned bhi[8][4];
#pragma unroll
        for (int p = 0; p < 8; p++)
            ldsm4(bhi[p], wh + boff0 + (unsigned)p * 16 * PB + ka);
#pragma unroll
        for (int p = 0; p < 8; p++) {
            mma16816(C[2 * p],     ah, bhi[p][0], bhi[p][1]);
            mma16816(C[2 * p + 1], ah, bhi[p][2], bhi[p][3]);
        }
#pragma unroll
        for (int p = 0; p < 8; p++) {
            unsigned bl[4];
            ldsm4(bl, wl + boff0 + (unsigned)p * 16 * PB + ka);
            mma16816(C[2 * p],     ah, bl[0], bl[1]);
            mma16816(C[2 * p + 1], ah, bl[2], bl[3]);
        }
#pragma unroll
        for (int p = 0; p < 8; p++) {
            mma16816(C[2 * p],     al, bhi[p][0], bhi[p][1]);
            mma16816(C[2 * p + 1], al, bhi[p][2], bhi[p][3]);
        }
    }
}

__device__ __forceinline__ void zero_C(float C[16][4])
{
#pragma unroll
    for (int t = 0; t < 16; t++) C[t][0] = C[t][1] = C[t][2] = C[t][3] = 0.f;
}

__device__ __forceinline__ void epilogue_to_smem(
    const float C[16][4], const float* __restrict__ bias,
    float* sE, int warp, int g, int tg)
{
    const int r0 = warp * 16 + g, r1 = r0 + 8;
#pragma unroll
    for (int t = 0; t < 16; t++) {
        int c = t * 8 + tg * 2;
        float2 bv = *(const float2*)(bias + c);
        sE[r0 * EPITCH + c]     = fmaxf(C[t][0] + bv.x, 0.f);
        sE[r0 * EPITCH + c + 1] = fmaxf(C[t][1] + bv.y, 0.f);
        sE[r1 * EPITCH + c]     = fmaxf(C[t][2] + bv.x, 0.f);
        sE[r1 * EPITCH + c + 1] = fmaxf(C[t][3] + bv.y, 0.f);
    }
}

__device__ __forceinline__ void epilogue_to_smem2(
    const float C[2][16][4], const float* __restrict__ bias,
    float* sE, int warp, int g, int tg)
{
#pragma unroll
    for (int rt = 0; rt < 2; rt++) {
        const int r0 = warp * 32 + rt * 16 + g, r1 = r0 + 8;
#pragma unroll
        for (int t = 0; t < 16; t++) {
            int c = t * 8 + tg * 2;
            float2 bv = *(const float2*)(bias + c);
            sE[r0 * EPITCH + c]     = fmaxf(C[rt][t][0] + bv.x, 0.f);
            sE[r0 * EPITCH + c + 1] = fmaxf(C[rt][t][1] + bv.y, 0.f);
            sE[r1 * EPITCH + c]     = fmaxf(C[rt][t][2] + bv.x, 0.f);
            sE[r1 * EPITCH + c + 1] = fmaxf(C[rt][t][3] + bv.y, 0.f);
        }
    }
}

__device__ __forceinline__ void mean4_red(
    const float* sE, float* __restrict__ T2, int og0, int G, int nrows, int tid)
{
    int col = tid & 127;
    for (int q = tid >> 7; q < (nrows >> 2); q += 2) {
        int og = og0 + q;
        if (og < G) {
            float v = sE[(4 * q) * EPITCH + col] + sE[(4 * q + 1) * EPITCH + col]
                    + sE[(4 * q + 2) * EPITCH + col] + sE[(4 * q + 3) * EPITCH + col];
            T2[(size_t)og * 128 + col] = 0.25f * v;
        }
    }
}

__device__ __forceinline__ void pairadd_red(
    const float* sE, const float* __restrict__ init, float* __restrict__ OUT,
    int og0, int Mout, int nrows, int tid)
{
    int col = tid & 127;
    for (int q = tid >> 7; q < (nrows >> 1); q += 2) {
        int og = og0 + q;
        if (og < Mout) {
            float v = sE[(2 * q) * EPITCH + col] + sE[(2 * q + 1) * EPITCH + col];
            OUT[(size_t)og * 128 + col] = init[(size_t)og * 128 + col] + 0.5f * v;
        }
    }
}

__device__ __forceinline__ void combine_red(
    const float* sE, const float* __restrict__ CTH, float* __restrict__ OUT,
    int row0, int M1, int nrows, int tid)
{
    int col = tid & 127;
    for (int q = tid >> 7; q < (nrows >> 2); q += 2) {
        int base = row0 + 4 * q;
        if (base < M1) {
            float s = sE[(4 * q) * EPITCH + col] + sE[(4 * q + 1) * EPITCH + col]
                    + sE[(4 * q + 2) * EPITCH + col] + sE[(4 * q + 3) * EPITCH + col];
            float tot = CTH[(size_t)(base >> 3) * 128 + col] + s;
#pragma unroll
            for (int s4 = 0; s4 < 4; s4++)
                OUT[(size_t)(base + s4) * 128 + col] =
                    0.25f * (tot - sE[(4 * q + s4) * EPITCH + col]);
        }
    }
}

// ================= big-level kernels (256-row tiles) =================
#define SMEM_BIG ((2 * STILE + 2 * XTILE) * (int)sizeof(__nv_bfloat16))

__global__ void __launch_bounds__(256, 1) gemm_relu_big(
    const float* __restrict__ X, const float* __restrict__ W,
    const float* __restrict__ bias, float* __restrict__ Y, int M)
{
    extern __shared__ __nv_bfloat16 sm[];
    __nv_bfloat16 *sWhi = sm, *sWlo = sm + STILE;
    __nv_bfloat16 *sXhi = sm + 2 * STILE, *sXlo = sm + 2 * STILE + XTILE;
    const int tid = threadIdx.x, lane = tid & 31, warp = tid >> 5;
    const int g = lane >> 2, tg = lane & 3;
    const int row0 = blockIdx.x * 256;

    stage_tile<128>(W, 128, 128, sWhi, sWlo, tid);
    stage_tile<256>(X + (size_t)row0 * 128, M - row0, 128, sXhi, sXlo, tid);
    __syncthreads();
    float C[2][16][4]; zero_C(C[0]); zero_C(C[1]);
    panel_mma2_v2(sWhi, sWlo, sXhi, sXlo, warp, lane, C);

#pragma unroll
    for (int rt = 0; rt < 2; rt++) {
        const int r0 = row0 + warp * 32 + rt * 16 + g, r1 = r0 + 8;
#pragma unroll
        for (int t = 0; t < 16; t++) {
            int c = t * 8 + tg * 2;
            float2 bv = *(const float2*)(bias + c);
            if (r0 < M) *(float2*)(Y + (size_t)r0 * 128 + c) =
                make_float2(fmaxf(C[rt][t][0] + bv.x, 0.f), fmaxf(C[rt][t][1] + bv.y, 0.f));
            if (r1 < M) *(float2*)(Y + (size_t)r1 * 128 + c) =
                make_float2(fmaxf(C[rt][t][2] + bv.x, 0.f), fmaxf(C[rt][t][3] + bv.y, 0.f));
        }
    }
}

__global__ void __launch_bounds__(256, 1) up_mean4_big(
    const float* __restrict__ X, const float* __restrict__ W,
    const float* __restrict__ bias, float* __restrict__ T2, int M1)
{
    extern __shared__ __nv_bfloat16 sm[];
    __nv_bfloat16 *sWhi = sm, *sWlo = sm + STILE;
    __nv_bfloat16 *sXhi = sm + 2 * STILE, *sXlo = sm + 2 * STILE + XTILE;
    float* sE = (float*)(sm + 2 * STILE);
    const int tid = threadIdx.x, lane = tid & 31, warp = tid >> 5;
    const int g = lane >> 2, tg = lane & 3;
    const int row0 = blockIdx.x * 256;

    stage_tile<128>(W, 128, 128, sWhi, sWlo, tid);
    stage_tile<256>(X + (size_t)row0 * 128, M1 - row0, 128, sXhi, sXlo, tid);
    __syncthreads();
    float C[2][16][4]; zero_C(C[0]); zero_C(C[1]);
    panel_mma2_v2(sWhi, sWlo, sXhi, sXlo, warp, lane, C);
    __syncthreads();
    epilogue_to_smem2(C, bias, sE, warp, g, tg);
    __syncthreads();
    mean4_red(sE, T2, row0 >> 2, M1 >> 2, 256, tid);
}

__global__ void __launch_bounds__(256, 1) up_pairadd_big(
    const float* __restrict__ X, const float* __restrict__ W,
    const float* __restrict__ bias, const float* __restrict__ init,
    float* __restrict__ AGG, int G)
{
    extern __shared__ __nv_bfloat16 sm[];
    __nv_bfloat16 *sWhi = sm, *sWlo = sm + STILE;
    __nv_bfloat16 *sXhi = sm + 2 * STILE, *sXlo = sm + 2 * STILE + XTILE;
    float* sE = (float*)(sm + 2 * STILE);
    const int tid = threadIdx.x, lane = tid & 31, warp = tid >> 5;
    const int g = lane >> 2, tg = lane & 3;
    const int row0 = blockIdx.x * 256;

    stage_tile<128>(W, 128, 128, sWhi, sWlo, tid);
    stage_tile<256>(X + (size_t)row0 * 128, G - row0, 128, sXhi, sXlo, tid);
    __syncthreads();
    float C[2][16][4]; zero_C(C[0]); zero_C(C[1]);
    panel_mma2_v2(sWhi, sWlo, sXhi, sXlo, warp, lane, C);
    __syncthreads();
    epilogue_to_smem2(C, bias, sE, warp, g, tg);
    __syncthreads();
    pairadd_red(sE, init, AGG, row0 >> 1, G >> 1, 256, tid);
}

__global__ void __launch_bounds__(256, 1) down_combine_big(
    const float* __restrict__ X, const float* __restrict__ W,
    const float* __restrict__ bias, const float* __restrict__ CTH,
    float* __restrict__ OUT, int M1)
{
    extern __shared__ __nv_bfloat16 sm[];
    __nv_bfloat16 *sWhi = sm, *sWlo = sm + STILE;
    __nv_bfloat16 *sXhi = sm + 2 * STILE, *sXlo = sm + 2 * STILE + XTILE;
    float* sE = (float*)(sm + 2 * STILE);
    const int tid = threadIdx.x, lane = tid & 31, warp = tid >> 5;
    const int g = lane >> 2, tg = lane & 3;
    const int row0 = blockIdx.x * 256;

    stage_tile<128>(W, 128, 128, sWhi, sWlo, tid);
    stage_tile<256>(X + (size_t)row0 * 128, M1 - row0, 128, sXhi, sXlo, tid);
    __syncthreads();
    float C[2][16][4]; zero_C(C[0]); zero_C(C[1]);
    panel_mma2_v2(sWhi, sWlo, sXhi, sXlo, warp, lane, C);
    __syncthreads();
    epilogue_to_smem2(C, bias, sE, warp, g, tg);
    __syncthreads();
    combine_red(sE, CTH, OUT, row0, M1, 256, tid);
}

__global__ void __launch_bounds__(256, 1) final_big(
    const float* __restrict__ CTX,
    const float* __restrict__ AGGa, const float* __restrict__ AGGb, int bnd,
    const float* __restrict__ Wf, const float* __restrict__ bf,
    const float* __restrict__ Wh, const float* __restrict__ bh,
    float* __restrict__ out, int M)
{
    extern __shared__ __nv_bfloat16 sm[];
    __nv_bfloat16 *sWhi = sm, *sWlo = sm + STILE;
    __nv_bfloat16 *sXhi = sm + 2 * STILE, *sXlo = sm + 2 * STILE + XTILE;
    const int tid = threadIdx.x, lane = tid & 31, warp = tid >> 5;
    const int g = lane >> 2, tg = lane & 3;
    const int row0 = blockIdx.x * 256;

    float C[2][16][4]; zero_C(C[0]); zero_C(C[1]);
    for (int p = 0; p < 2; p++) {
        __syncthreads();
        stage_tile<128>(Wf + p * 128, 128, 256, sWhi, sWlo, tid);
        if (p == 0)
            stage_tile<256>(CTX + (size_t)row0 * 128, M - row0, 128, sXhi, sXlo, tid);
        else
            stage_tile_sel(AGGa, AGGb, bnd, row0, M, sXhi, sXlo, tid);
        __syncthreads();
        panel_mma2_v2(sWhi, sWlo, sXhi, sXlo, warp, lane, C);
    }

#pragma unroll
    for (int rt = 0; rt < 2; rt++) {
        float s0 = 0.f, s1 = 0.f;
#pragma unroll
        for (int t = 0; t < 16; t++) {
            int c = t * 8 + tg * 2;
            float2 bv = *(const float2*)(bf + c);
            float2 wv = *(const float2*)(Wh + c);
            s0 += fmaxf(C[rt][t][0] + bv.x, 0.f) * wv.x + fmaxf(C[rt][t][1] + bv.y, 0.f) * wv.y;
            s1 += fmaxf(C[rt][t][2] + bv.x, 0.f) * wv.x + fmaxf(C[rt][t][3] + bv.y, 0.f) * wv.y;
        }
        s0 += __shfl_xor_sync(0xffffffffu, s0, 1);
        s0 += __shfl_xor_sync(0xffffffffu, s0, 2);
        s1 += __shfl_xor_sync(0xffffffffu, s1, 1);
        s1 += __shfl_xor_sync(0xffffffffu, s1, 2);
        if (tg == 0) {
            const int r0 = row0 + warp * 32 + rt * 16 + g, r1 = r0 + 8;
            float bhv = bh[0];
            if (r0 < M) out[r0] = s0 + bhv;
            if (r1 < M) out[r1] = s1 + bhv;
        }
    }
}

// ================= tiny-level kernels =================
#define SMEM_SMALL (4 * STILE * (int)sizeof(__nv_bfloat16))

__global__ void __launch_bounds__(256) up_small(
    const float* __restrict__ Xc, const float* __restrict__ init_l,
    float* __restrict__ AGG,
    const float* __restrict__ Ws, const float* __restrict__ bs,
    const float* __restrict__ Wc, const float* __restrict__ bc,
    float* __restrict__ T2, int M1)
{
    extern __shared__ __nv_bfloat16 sm[];
    __nv_bfloat16 *sWhi = sm, *sWlo = sm + STILE, *sXhi = sm + 2 * STILE, *sXlo = sm + 3 * STILE;
    float* sE = (float*)(sm + 2 * STILE);
    const int tid = threadIdx.x, lane = tid & 31, warp = tid >> 5;
    const int g = lane >> 2, tg = lane & 3;
    const int G = M1 >> 2, Mout = M1 >> 3;

    stage_tile<128>(Ws, 128, 128, sWhi, sWlo, tid);
    stage_tile<128>(Xc, M1, 128, sXhi, sXlo, tid);
    __syncthreads();
    {
        float C[16][4]; zero_C(C);
        panel_mma1_v2(sWhi, sWlo, sXhi, sXlo, warp, lane, C);
        __syncthreads();
        epilogue_to_smem(C, bs, sE, warp, g, tg);
        __syncthreads();
        mean4_red(sE, T2, 0, G, 128, tid);
    }
    __syncthreads();
    stage_tile<128>(Wc, 128, 128, sWhi, sWlo, tid);
    stage_tile<128>(T2, G, 128, sXhi, sXlo, tid);
    __syncthreads();
    {
        float C[16][4]; zero_C(C);
        panel_mma1_v2(sWhi, sWlo, sXhi, sXlo, warp, lane, C);
        __syncthreads();
        epilogue_to_smem(C, bc, sE, warp, g, tg);
        __syncthreads();
        pairadd_red(sE, init_l, AGG, 0, Mout, 128, tid);
    }
}

__global__ void __launch_bounds__(256) down_small(
    const float* __restrict__ ctx_l, const float* __restrict__ aggc,
    const float* __restrict__ Wx, const float* __restrict__ bx,
    float* __restrict__ T2, float* __restrict__ ctx_out, int Ml, int M1)
{
    extern __shared__ __nv_bfloat16 sm[];
    __nv_bfloat16 *sWhi = sm, *sWlo = sm + STILE, *sXhi = sm + 2 * STILE, *sXlo = sm + 3 * STILE;
    float* sE = (float*)(sm + 2 * STILE);
    const int tid = threadIdx.x, lane = tid & 31, warp = tid >> 5;
    const int g = lane >> 2, tg = lane & 3;

    stage_tile<128>(Wx, 128, 128, sWhi, sWlo, tid);
    stage_tile<128>(ctx_l, Ml, 128, sXhi, sXlo, tid);
    __syncthreads();
    {
        float C[16][4]; zero_C(C);
        panel_mma1_v2(sWhi, sWlo, sXhi, sXlo, warp, lane, C);
        const int r0 = warp * 16 + g, r1 = r0 + 8;
#pragma unroll
        for (int t = 0; t < 16; t++) {
            int c = t * 8 + tg * 2;
            float2 bv = *(const float2*)(bx + c);
            if (r0 < Ml) *(float2*)(T2 + (size_t)r0 * 128 + c) =
                make_float2(fmaxf(C[t][0] + bv.x, 0.f), fmaxf(C[t][1] + bv.y, 0.f));
            if (r1 < Ml) *(float2*)(T2 + (size_t)r1 * 128 + c) =
                make_float2(fmaxf(C[t][2] + bv.x, 0.f), fmaxf(C[t][3] + bv.y, 0.f));
        }
    }
    __syncthreads();
    stage_tile<128>(aggc, M1, 128, sXhi, sXlo, tid);
    __syncthreads();
    {
        float C[16][4]; zero_C(C);
        panel_mma1_v2(sWhi, sWlo, sXhi, sXlo, warp, lane, C);
        __syncthreads();
        epilogue_to_smem(C, bx, sE, warp, g, tg);
        __syncthreads();
        combine_red(sE, T2, ctx_out, 0, M1, 128, tid);
    }
}

__global__ void set_ones(float* p, int n)
{
    int i = blockIdx.x * blockDim.x + threadIdx.x;
    if (i < n) p[i] = 1.0f;
}

// ---------------- launch ----------------
extern "C" void kernel_launch(void* const* d_in, const int* in_sizes, int n_in,
                              void* d_out, int out_size)
{
    const float* initial = (const float*)d_in[0];
    const float* Ws = (const float*)d_in[1];
    const float* bs = (const float*)d_in[2];
    const float* Wc = (const float*)d_in[3];
    const float* bc = (const float*)d_in[4];
    const float* Wx = (const float*)d_in[5];
    const float* bx = (const float*)d_in[6];
    const float* Wf = (const float*)d_in[7];
    const float* bf = (const float*)d_in[8];
    const float* Wh = (const float*)d_in[9];
    const float* bh = (const float*)d_in[10];
    float* out = (float*)d_out;

    float *p_agg, *p_ctx, *p_t2;
    cudaGetSymbolAddress((void**)&p_agg, g_agg);
    cudaGetSymbolAddress((void**)&p_ctx, g_ctx);
    cudaGetSymbolAddress((void**)&p_t2,  g_t2);

    cudaFuncSetAttribute(gemm_relu_big,    cudaFuncAttributeMaxDynamicSharedMemorySize, SMEM_BIG);
    cudaFuncSetAttribute(up_mean4_big,     cudaFuncAttributeMaxDynamicSharedMemorySize, SMEM_BIG);
    cudaFuncSetAttribute(up_pairadd_big,   cudaFuncAttributeMaxDynamicSharedMemorySize, SMEM_BIG);
    cudaFuncSetAttribute(down_combine_big, cudaFuncAttributeMaxDynamicSharedMemorySize, SMEM_BIG);
    cudaFuncSetAttribute(final_big,        cudaFuncAttributeMaxDynamicSharedMemorySize, SMEM_BIG);
    cudaFuncSetAttribute(up_small,         cudaFuncAttributeMaxDynamicSharedMemorySize, SMEM_SMALL);
    cudaFuncSetAttribute(down_small,       cudaFuncAttributeMaxDynamicSharedMemorySize, SMEM_SMALL);

    const float* leaf_agg = initial + (size_t)H_OFFS[6] * DIM;

    // ---- up pass ----
    for (int l = 5; l >= 2; l--) {
        int M1 = H_SIZES[l + 1];
        int G  = M1 >> 2;
        const float* Xc = (l == 5) ? leaf_agg : (p_agg + (size_t)H_OFFS[l + 1] * DIM);

        up_mean4_big<<<(M1 + 255) / 256, 256, SMEM_BIG>>>(Xc, Ws, bs, p_t2, M1);
        up_pairadd_big<<<(G + 255) / 256, 256, SMEM_BIG>>>(
            p_t2, Wc, bc,
            initial + (size_t)H_OFFS[l] * DIM,
            p_agg + (size_t)H_OFFS[l] * DIM, G);
    }
    for (int l = 1; l >= 0; l--) {
        up_small<<<1, 256, SMEM_SMALL>>>(
            p_agg + (size_t)H_OFFS[l + 1] * DIM,
            initial + (size_t)H_OFFS[l] * DIM,
            p_agg + (size_t)H_OFFS[l] * DIM,
            Ws, bs, Wc, bc, p_t2, H_SIZES[l + 1]);
    }

    // ---- down pass ----
    set_ones<<<1, 128>>>(p_ctx, DIM);
    for (int l = 0; l < 2; l++) {
        down_small<<<1, 256, SMEM_SMALL>>>(
            p_ctx + (size_t)H_OFFS[l] * DIM,
            p_agg + (size_t)H_OFFS[l + 1] * DIM,
            Wx, bx, p_t2,
            p_ctx + (size_t)H_OFFS[l + 1] * DIM, H_SIZES[l], H_SIZES[l + 1]);
    }
    for (int l = 2; l < 6; l++) {
        int Ml = H_SIZES[l], M1 = H_SIZES[l + 1];
        const float* Xc = (l == 5) ? leaf_agg : (p_agg + (size_t)H_OFFS[l + 1] * DIM);

        gemm_relu_big<<<(Ml + 255) / 256, 256, SMEM_BIG>>>(
            p_ctx + (size_t)H_OFFS[l] * DIM, Wx, bx, p_t2, Ml);
        down_combine_big<<<(M1 + 255) / 256, 256, SMEM_BIG>>>(
            Xc, Wx, bx, p_t2,
            p_ctx + (size_t)H_OFFS[l + 1] * DIM, M1);
    }

    // ---- final ----
    final_big<<<(N_TOTAL + 255) / 256, 256, SMEM_BIG>>>(
        p_ctx, p_agg, initial, NTOP,
        Wf, bf, Wh, bh, out, N_TOTAL);
}